// round 8
// baseline (speedup 1.0000x reference)
#include <cuda_runtime.h>
#include <cuda_fp16.h>
#include <mma.h>
#include <cstdint>

using namespace nvcuda;

// ---------------------------------------------------------------------------
#define BATCH 4
#define SEQ 2048
#define ROWS (BATCH * SEQ)       // 8192
#define DMODEL 1024
#define NHEADS 16
#define DHEAD 64
#define DFF 4096

// ---------------------------------------------------------------------------
// Scratch (static device globals; no allocation allowed)
// ---------------------------------------------------------------------------
__device__ __half g_xh[ROWS * DMODEL];
__device__ __half g_xl[ROWS * DMODEL];
__device__ __half g_wqh[DMODEL * DMODEL];
__device__ __half g_wql[DMODEL * DMODEL];
__device__ __half g_wkh[DMODEL * DMODEL];
__device__ __half g_wkl[DMODEL * DMODEL];
__device__ __half g_wvh[DMODEL * DMODEL];
__device__ __half g_woh[DMODEL * DMODEL];
__device__ __half g_w1h[DMODEL * DFF];
__device__ __half g_w2h[DFF * DMODEL];

__device__ float  g_q[ROWS * DMODEL];
__device__ float  g_k[ROWS * DMODEL];
__device__ __half g_qrh[ROWS * DMODEL];
__device__ __half g_qrl[ROWS * DMODEL];
__device__ __half g_krh[ROWS * DMODEL];
__device__ __half g_krl[ROWS * DMODEL];
__device__ __half g_vh[ROWS * DMODEL];
__device__ __half g_ctx[ROWS * DMODEL];
__device__ float  g_res1[ROWS * DMODEL];
__device__ float  g_hbuf[ROWS * DMODEL];
__device__ __half g_hh[ROWS * DMODEL];
__device__ __half g_ff1[ROWS * DFF];
__device__ float  g_res2[ROWS * DMODEL];

// ---------------------------------------------------------------------------
// cp.async helpers
// ---------------------------------------------------------------------------
__device__ __forceinline__ void cp16(void* s, const void* g) {
    unsigned int sa = (unsigned int)__cvta_generic_to_shared(s);
    asm volatile("cp.async.cg.shared.global [%0], [%1], 16;\n" :: "r"(sa), "l"(g) : "memory");
}
__device__ __forceinline__ void cp_commit() {
    asm volatile("cp.async.commit_group;\n" ::: "memory");
}
template<int N> __device__ __forceinline__ void cp_wait() {
    asm volatile("cp.async.wait_group %0;\n" :: "n"(N) : "memory");
}

// ---------------------------------------------------------------------------
// fp32 -> fp16 conversion (plain and hi/lo split)
// ---------------------------------------------------------------------------
__global__ void __launch_bounds__(256) f2h_kernel(const float* __restrict__ in,
                                                  __half* __restrict__ out, int n4) {
    int i = blockIdx.x * 256 + threadIdx.x;
    if (i < n4) {
        float4 v = ((const float4*)in)[i];
        ((__half2*)out)[2 * i]     = __floats2half2_rn(v.x, v.y);
        ((__half2*)out)[2 * i + 1] = __floats2half2_rn(v.z, v.w);
    }
}

__global__ void __launch_bounds__(256) f2h_split_kernel(const float* __restrict__ in,
                                                        __half* __restrict__ hi,
                                                        __half* __restrict__ lo, int n4) {
    int i = blockIdx.x * 256 + threadIdx.x;
    if (i < n4) {
        float4 v = ((const float4*)in)[i];
        __half hx = __float2half(v.x), hy = __float2half(v.y);
        __half hz = __float2half(v.z), hw = __float2half(v.w);
        ((__half2*)hi)[2 * i]     = __halves2half2(hx, hy);
        ((__half2*)hi)[2 * i + 1] = __halves2half2(hz, hw);
        ((__half2*)lo)[2 * i]     = __floats2half2_rn(v.x - __half2float(hx),
                                                      v.y - __half2float(hy));
        ((__half2*)lo)[2 * i + 1] = __floats2half2_rn(v.z - __half2float(hz),
                                                      v.w - __half2float(hw));
    }
}

// ---------------------------------------------------------------------------
// Plain fp16 GEMM, 128x128x32 tiles, cp.async 3-stage pipeline, one barrier
// per k-iter. 256 threads = 8 warps (4x2), warp tile 32x64.
// ---------------------------------------------------------------------------
#define GH_STAGE_H 10496
#define GH_SMEM 67584

template<bool RELU, bool RESID, bool WF32, bool WF16>
__global__ void __launch_bounds__(256) gemm_h(
    const __half* __restrict__ A, const __half* __restrict__ Bw,
    const float* __restrict__ bias, const float* __restrict__ resid,
    float* __restrict__ Cf, __half* __restrict__ Ch,
    int M, int N, int K)
{
    extern __shared__ __align__(16) unsigned char sm[];
    __half* SH = (__half*)sm;

    const int tid = threadIdx.x;
    const int warp = tid >> 5;
    const int wm = warp >> 1;
    const int wn = warp & 1;
    const int row0 = blockIdx.y * 128;
    const int col0 = blockIdx.x * 128;

    wmma::fragment<wmma::accumulator, 16, 16, 16, float> acc[2][4];
#pragma unroll
    for (int i = 0; i < 2; i++)
#pragma unroll
        for (int j = 0; j < 4; j++) wmma::fill_fragment(acc[i][j], 0.f);

    auto load_stage = [&](int k0, int s) {
        __half* As = SH + s * GH_STAGE_H;
        __half* Bs = As + 6144;
#pragma unroll
        for (int i = 0; i < 2; i++) {
            int c = tid + i * 256;
            int r = c >> 2, q = c & 3;
            cp16(As + r * 48 + q * 8, A + (size_t)(row0 + r) * K + k0 + q * 8);
        }
#pragma unroll
        for (int i = 0; i < 2; i++) {
            int c = tid + i * 256;
            int r = c >> 4, q = c & 15;
            cp16(Bs + r * 136 + q * 8, Bw + (size_t)(k0 + r) * N + col0 + q * 8);
        }
    };

    const int nk = K >> 5;
    load_stage(0, 0); cp_commit();
    load_stage(32, 1); cp_commit();
    for (int kt = 0; kt < nk; kt++) {
        if (kt + 1 < nk) cp_wait<1>(); else cp_wait<0>();
        __syncthreads();
        if (kt + 2 < nk) { load_stage((kt + 2) << 5, (kt + 2) % 3); cp_commit(); }
        __half* As = SH + (kt % 3) * GH_STAGE_H;
        __half* Bs = As + 6144;
#pragma unroll
        for (int kk = 0; kk < 2; kk++) {
            wmma::fragment<wmma::matrix_a, 16, 16, 16, __half, wmma::row_major> af[2];
            wmma::fragment<wmma::matrix_b, 16, 16, 16, __half, wmma::row_major> bf[4];
#pragma unroll
            for (int i = 0; i < 2; i++)
                wmma::load_matrix_sync(af[i], As + (wm * 32 + i * 16) * 48 + kk * 16, 48);
#pragma unroll
            for (int j = 0; j < 4; j++)
                wmma::load_matrix_sync(bf[j], Bs + (kk * 16) * 136 + wn * 64 + j * 16, 136);
#pragma unroll
            for (int i = 0; i < 2; i++)
#pragma unroll
                for (int j = 0; j < 4; j++)
                    wmma::mma_sync(acc[i][j], af[i], bf[j], acc[i][j]);
        }
    }
    __syncthreads();

    float* stg = (float*)sm;
#pragma unroll
    for (int i = 0; i < 2; i++)
#pragma unroll
        for (int j = 0; j < 4; j++)
            wmma::store_matrix_sync(stg + (wm * 32 + i * 16) * 132 + wn * 64 + j * 16,
                                    acc[i][j], 132, wmma::mem_row_major);
    __syncthreads();

#pragma unroll
    for (int e = 0; e < 16; e++) {
        int idx = tid + e * 256;
        int r = idx >> 5, c4 = idx & 31;
        float4 v = *(float4*)(stg + r * 132 + c4 * 4);
        float4 bb = *(const float4*)(bias + col0 + c4 * 4);
        v.x += bb.x; v.y += bb.y; v.z += bb.z; v.w += bb.w;
        if (RELU) { v.x = fmaxf(v.x, 0.f); v.y = fmaxf(v.y, 0.f); v.z = fmaxf(v.z, 0.f); v.w = fmaxf(v.w, 0.f); }
        size_t g = (size_t)(row0 + r) * N + col0 + c4 * 4;
        if (RESID) {
            float4 rr = *(const float4*)(resid + g);
            v.x += rr.x; v.y += rr.y; v.z += rr.z; v.w += rr.w;
        }
        if (WF32) *(float4*)(Cf + g) = v;
        if (WF16) {
            ((__half2*)(Ch + g))[0] = __floats2half2_rn(v.x, v.y);
            ((__half2*)(Ch + g))[1] = __floats2half2_rn(v.z, v.w);
        }
    }
}

// ---------------------------------------------------------------------------
// Split-fp16 GEMM (fp32-accurate), 2-stage single-barrier pipeline, fp32 out.
// ---------------------------------------------------------------------------
#define GS_STAGE_H 20992
#define GS_SMEM 83968

__global__ void __launch_bounds__(256) gemm_split(
    const __half* __restrict__ Ah_, const __half* __restrict__ Al_,
    const __half* __restrict__ Bh_, const __half* __restrict__ Bl_,
    const float* __restrict__ bias, float* __restrict__ Cf,
    int M, int N, int K)
{
    extern __shared__ __align__(16) unsigned char sm[];
    __half* SH = (__half*)sm;

    const int tid = threadIdx.x;
    const int warp = tid >> 5;
    const int wm = warp >> 1;
    const int wn = warp & 1;
    const int row0 = blockIdx.y * 128;
    const int col0 = blockIdx.x * 128;

    wmma::fragment<wmma::accumulator, 16, 16, 16, float> acc[2][4];
#pragma unroll
    for (int i = 0; i < 2; i++)
#pragma unroll
        for (int j = 0; j < 4; j++) wmma::fill_fragment(acc[i][j], 0.f);

    auto load_stage = [&](int k0, int s) {
        __half* Ahs = SH + s * GS_STAGE_H;
        __half* Als = Ahs + 6144;
        __half* Bhs = Als + 6144;
        __half* Bls = Bhs + 4352;
#pragma unroll
        for (int i = 0; i < 2; i++) {
            int c = tid + i * 256;
            int r = c >> 2, q = c & 3;
            size_t g = (size_t)(row0 + r) * K + k0 + q * 8;
            cp16(Ahs + r * 48 + q * 8, Ah_ + g);
            cp16(Als + r * 48 + q * 8, Al_ + g);
        }
#pragma unroll
        for (int i = 0; i < 2; i++) {
            int c = tid + i * 256;
            int r = c >> 4, q = c & 15;
            size_t g = (size_t)(k0 + r) * N + col0 + q * 8;
            cp16(Bhs + r * 136 + q * 8, Bh_ + g);
            cp16(Bls + r * 136 + q * 8, Bl_ + g);
        }
    };

    const int nk = K >> 5;
    load_stage(0, 0); cp_commit();
    for (int kt = 0; kt < nk; kt++) {
        cp_wait<0>();
        __syncthreads();
        if (kt + 1 < nk) { load_stage((kt + 1) << 5, (kt + 1) & 1); cp_commit(); }
        __half* Ahs = SH + (kt & 1) * GS_STAGE_H;
        __half* Als = Ahs + 6144;
        __half* Bhs = Als + 6144;
        __half* Bls = Bhs + 4352;
#pragma unroll
        for (int kk = 0; kk < 2; kk++) {
            wmma::fragment<wmma::matrix_a, 16, 16, 16, __half, wmma::row_major> afh[2], afl[2];
            wmma::fragment<wmma::matrix_b, 16, 16, 16, __half, wmma::row_major> bfh[4], bfl[4];
#pragma unroll
            for (int i = 0; i < 2; i++) {
                wmma::load_matrix_sync(afh[i], Ahs + (wm * 32 + i * 16) * 48 + kk * 16, 48);
                wmma::load_matrix_sync(afl[i], Als + (wm * 32 + i * 16) * 48 + kk * 16, 48);
            }
#pragma unroll
            for (int j = 0; j < 4; j++) {
                wmma::load_matrix_sync(bfh[j], Bhs + (kk * 16) * 136 + wn * 64 + j * 16, 136);
                wmma::load_matrix_sync(bfl[j], Bls + (kk * 16) * 136 + wn * 64 + j * 16, 136);
            }
#pragma unroll
            for (int i = 0; i < 2; i++)
#pragma unroll
                for (int j = 0; j < 4; j++) {
                    wmma::mma_sync(acc[i][j], afh[i], bfh[j], acc[i][j]);
                    wmma::mma_sync(acc[i][j], afh[i], bfl[j], acc[i][j]);
                    wmma::mma_sync(acc[i][j], afl[i], bfh[j], acc[i][j]);
                }
        }
    }
    __syncthreads();

    float* stg = (float*)sm;
#pragma unroll
    for (int i = 0; i < 2; i++)
#pragma unroll
        for (int j = 0; j < 4; j++)
            wmma::store_matrix_sync(stg + (wm * 32 + i * 16) * 132 + wn * 64 + j * 16,
                                    acc[i][j], 132, wmma::mem_row_major);
    __syncthreads();

#pragma unroll
    for (int e = 0; e < 16; e++) {
        int idx = tid + e * 256;
        int r = idx >> 5, c4 = idx & 31;
        float4 v = *(float4*)(stg + r * 132 + c4 * 4);
        float4 bb = *(const float4*)(bias + col0 + c4 * 4);
        v.x += bb.x; v.y += bb.y; v.z += bb.z; v.w += bb.w;
        *(float4*)(Cf + (size_t)(row0 + r) * N + col0 + c4 * 4) = v;
    }
}

// ---------------------------------------------------------------------------
// "RoPE" exactly as the reference defines it: multiply by the raw ANGLES
// (no cos/sin). q pre-scaled by 1/sqrt(Dh). Outputs hi/lo fp16 splits.
// Identical numerics to the round-5 passing kernel.
// ---------------------------------------------------------------------------
__global__ void __launch_bounds__(256) rope_kernel(
    const float* __restrict__ q, const float* __restrict__ k,
    __half* __restrict__ qrh, __half* __restrict__ qrl,
    __half* __restrict__ krh, __half* __restrict__ krl)
{
    __shared__ float sInv[32];
    int tid = threadIdx.x;
    if (tid < 32)
        sInv[tid] = (float)exp(-0.28782313662425575 * (double)tid); // ln(1e4)/32
    __syncthreads();

    int row = blockIdx.x;
    int s = row & (SEQ - 1);
    float fs = (float)s;

#pragma unroll
    for (int t = 0; t < 2; t++) {
        int idx = tid + t * 256;        // 0..511
        int head = idx >> 5;
        int j = idx & 31;
        int base = row * DMODEL + head * DHEAD;

        float t0 = q[base + 2 * j];
        float t1 = q[base + 2 * j + 1];
        float u0 = k[base + 2 * j];
        float u1 = k[base + 2 * j + 1];

        int ic = (2 * j < 32) ? 2 * j : 2 * j - 32;
        int is = (2 * j + 1 < 32) ? 2 * j + 1 : 2 * j - 31;
        float c  = fs * sInv[ic];   // raw angle, NOT cos
        float si = fs * sInv[is];   // raw angle, NOT sin

        float o0 = (t0 * c - t1 * si) * 0.125f;
        float o1 = (t0 * si + t1 * c) * 0.125f;
        __half h0 = __float2half(o0);
        __half h1 = __float2half(o1);
        qrh[base + j]      = h0;
        qrh[base + 32 + j] = h1;
        qrl[base + j]      = __float2half(o0 - __half2float(h0));
        qrl[base + 32 + j] = __float2half(o1 - __half2float(h1));

        float p0 = u0 * c - u1 * si;
        float p1 = u0 * si + u1 * c;
        __half g0 = __float2half(p0);
        __half g1 = __float2half(p1);
        krh[base + j]      = g0;
        krh[base + 32 + j] = g1;
        krl[base + j]      = __float2half(p0 - __half2float(g0));
        krl[base + 32 + j] = __float2half(p1 - __half2float(g1));
    }
}

// ---------------------------------------------------------------------------
// Flash attention: grid (SEQ/128, H, B), 256 threads (8 warps, 16 q-rows each).
// kh/kl/v 64x64 tiles staged in smem (cp.async 2-stage, one barrier/iter,
// shared by all 8 warps). Split-fp16 QK^T (3 MMAs). Per-warp math identical
// to the round-5 passing kernel.
// ---------------------------------------------------------------------------
#define ATT_SMEM 144384

__global__ void __launch_bounds__(256) attn_kernel(
    const __half* __restrict__ qh, const __half* __restrict__ ql,
    const __half* __restrict__ kh, const __half* __restrict__ kl,
    const __half* __restrict__ v, __half* __restrict__ ctx)
{
    extern __shared__ __align__(16) unsigned char sm[];
    __half* KH = (__half*)sm;                  // [2][64][72]
    __half* KL = KH + 9216;
    __half* VT = KL + 9216;
    float*  sS = (float*)(sm + 55296);         // [8][16][68]
    __half* sP = (__half*)(sm + 90112);        // [8][16][72]
    float*  sO = (float*)(sm + 108544);        // [8][16][68]
    float*  sM = (float*)(sm + 143360);        // [128]
    float*  sL = sM + 128;

    const int tid = threadIdx.x;
    const int w = tid >> 5;
    const int lane = tid & 31;
    const int qt = blockIdx.x;
    const int h = blockIdx.y;
    const int b = blockIdx.z;
    const int hc = h * DHEAD;
    const int brow = b * SEQ;
    const int qrow0 = brow + qt * 128 + w * 16;

    const int r = lane >> 1;
    const int half = lane & 1;

    if (half == 0) { sM[w * 16 + r] = -1e30f; sL[w * 16 + r] = 0.f; }
    {
        float* Orow = sO + (w * 16 + r) * 68 + half * 32;
#pragma unroll
        for (int c = 0; c < 32; c++) Orow[c] = 0.f;
    }

    wmma::fragment<wmma::matrix_a, 16, 16, 16, __half, wmma::row_major> qfh[4], qfl[4];
#pragma unroll
    for (int kk = 0; kk < 4; kk++) {
        wmma::load_matrix_sync(qfh[kk], qh + (size_t)qrow0 * DMODEL + hc + kk * 16, DMODEL);
        wmma::load_matrix_sync(qfl[kk], ql + (size_t)qrow0 * DMODEL + hc + kk * 16, DMODEL);
    }

    auto load_stage = [&](int kv, int s) {
#pragma unroll
        for (int i = 0; i < 2; i++) {
            int c = tid + i * 256;
            int rr = c >> 3, qq = c & 7;
            size_t g = (size_t)(brow + kv * 64 + rr) * DMODEL + hc + qq * 8;
            int so = s * 4608 + rr * 72 + qq * 8;
            cp16(KH + so, kh + g);
            cp16(KL + so, kl + g);
            cp16(VT + so, v + g);
        }
    };

    const int NT = SEQ / 64;
    load_stage(0, 0); cp_commit();

    for (int kt = 0; kt < NT; kt++) {
        cp_wait<0>();
        __syncthreads();
        if (kt + 1 < NT) { load_stage(kt + 1, (kt + 1) & 1); cp_commit(); }

        const int s = kt & 1;
        __half* KHs = KH + s * 4608;
        __half* KLs = KL + s * 4608;
        __half* VTs = VT + s * 4608;

        // ---- S = Q @ K^T (split: qh*kh + qh*kl + ql*kh) ----
#pragma unroll
        for (int kc = 0; kc < 4; kc++) {
            wmma::fragment<wmma::accumulator, 16, 16, 16, float> sacc;
            wmma::fill_fragment(sacc, 0.f);
#pragma unroll
            for (int kk = 0; kk < 4; kk++) {
                wmma::fragment<wmma::matrix_b, 16, 16, 16, __half, wmma::col_major> bfh, bfl;
                wmma::load_matrix_sync(bfh, KHs + (kc * 16) * 72 + kk * 16, 72);
                wmma::load_matrix_sync(bfl, KLs + (kc * 16) * 72 + kk * 16, 72);
                wmma::mma_sync(sacc, qfh[kk], bfh, sacc);
                wmma::mma_sync(sacc, qfh[kk], bfl, sacc);
                wmma::mma_sync(sacc, qfl[kk], bfh, sacc);
            }
            wmma::store_matrix_sync(sS + (w * 16) * 68 + kc * 16, sacc, 68, wmma::mem_row_major);
        }
        __syncwarp();

        // ---- online softmax (lane pairs split the 64 cols) ----
        {
            float* Srow = sS + (w * 16 + r) * 68 + half * 32;
            float mo = sM[w * 16 + r];
            float mt = -1e30f;
#pragma unroll
            for (int c = 0; c < 32; c++) mt = fmaxf(mt, Srow[c]);
            mt = fmaxf(mt, __shfl_xor_sync(0xffffffffu, mt, 1));
            float mn = fmaxf(mo, mt);
            float alpha = __expf(mo - mn);
            float sum = 0.f;
            __half* Prow = sP + (w * 16 + r) * 72 + half * 32;
#pragma unroll
            for (int c = 0; c < 32; c++) {
                float p = __expf(Srow[c] - mn);
                Prow[c] = __float2half(p);
                sum += p;
            }
            sum += __shfl_xor_sync(0xffffffffu, sum, 1);
            if (half == 0) {
                sL[w * 16 + r] = sL[w * 16 + r] * alpha + sum;
                sM[w * 16 + r] = mn;
            }
            float* Orow = sO + (w * 16 + r) * 68 + half * 32;
#pragma unroll
            for (int c = 0; c < 32; c++) Orow[c] *= alpha;
        }
        __syncwarp();

        // ---- O += P @ V ----
#pragma unroll
        for (int dc = 0; dc < 4; dc++) {
            wmma::fragment<wmma::accumulator, 16, 16, 16, float> oacc;
            wmma::load_matrix_sync(oacc, sO + (w * 16) * 68 + dc * 16, 68, wmma::mem_row_major);
#pragma unroll
            for (int kk = 0; kk < 4; kk++) {
                wmma::fragment<wmma::matrix_a, 16, 16, 16, __half, wmma::row_major> pf;
                wmma::load_matrix_sync(pf, sP + (w * 16) * 72 + kk * 16, 72);
                wmma::fragment<wmma::matrix_b, 16, 16, 16, __half, wmma::row_major> vf;
                wmma::load_matrix_sync(vf, VTs + (kk * 16) * 72 + dc * 16, 72);
                wmma::mma_sync(oacc, pf, vf, oacc);
            }
            wmma::store_matrix_sync(sO + (w * 16) * 68 + dc * 16, oacc, 68, wmma::mem_row_major);
        }
    }

    // ---- epilogue: O / l ----
    __syncwarp();
    {
        float inv = 1.f / sL[w * 16 + r];
        float* Orow = sO + (w * 16 + r) * 68 + half * 32;
        __half* dst = ctx + (size_t)(qrow0 + r) * DMODEL + hc + half * 32;
#pragma unroll
        for (int c = 0; c < 32; c++) dst[c] = __float2half(Orow[c] * inv);
    }
}

// ---------------------------------------------------------------------------
// LayerNorm over 1024 cols, block=256, one row per block. Optional fp16 copy.
// ---------------------------------------------------------------------------
__global__ void __launch_bounds__(256) ln_kernel(
    const float* __restrict__ in, const float* __restrict__ g,
    const float* __restrict__ be, float* __restrict__ outf,
    __half* __restrict__ outh)
{
    int row = blockIdx.x;
    int tid = threadIdx.x;
    float4 v = ((const float4*)(in + (size_t)row * DMODEL))[tid];
    float s  = v.x + v.y + v.z + v.w;
    float ss = v.x * v.x + v.y * v.y + v.z * v.z + v.w * v.w;
#pragma unroll
    for (int o = 16; o > 0; o >>= 1) {
        s  += __shfl_down_sync(0xffffffffu, s, o);
        ss += __shfl_down_sync(0xffffffffu, ss, o);
    }
    __shared__ float shs[8], shss[8], smu, srs;
    int lane = tid & 31, wid = tid >> 5;
    if (lane == 0) { shs[wid] = s; shss[wid] = ss; }
    __syncthreads();
    if (tid == 0) {
        float S = 0.f, SS = 0.f;
#pragma unroll
        for (int i = 0; i < 8; i++) { S += shs[i]; SS += shss[i]; }
        float mu = S * (1.f / 1024.f);
        float var = SS * (1.f / 1024.f) - mu * mu;
        smu = mu;
        srs = rsqrtf(var + 1e-5f);
    }
    __syncthreads();
    float mu = smu, rs = srs;
    float4 gv = ((const float4*)g)[tid];
    float4 bv = ((const float4*)be)[tid];
    float4 o;
    o.x = (v.x - mu) * rs * gv.x + bv.x;
    o.y = (v.y - mu) * rs * gv.y + bv.y;
    o.z = (v.z - mu) * rs * gv.z + bv.z;
    o.w = (v.w - mu) * rs * gv.w + bv.w;
    ((float4*)(outf + (size_t)row * DMODEL))[tid] = o;
    if (outh) {
        ((__half2*)(outh + (size_t)row * DMODEL))[2 * tid]     = __floats2half2_rn(o.x, o.y);
        ((__half2*)(outh + (size_t)row * DMODEL))[2 * tid + 1] = __floats2half2_rn(o.z, o.w);
    }
}

// ---------------------------------------------------------------------------
// launch
// ---------------------------------------------------------------------------
static inline void launch_f2h(const float* in, __half* out, int n) {
    int n4 = n / 4;
    f2h_kernel<<<(n4 + 255) / 256, 256>>>(in, out, n4);
}
static inline void launch_f2h_split(const float* in, __half* hi, __half* lo, int n) {
    int n4 = n / 4;
    f2h_split_kernel<<<(n4 + 255) / 256, 256>>>(in, hi, lo, n4);
}

extern "C" void kernel_launch(void* const* d_in, const int* in_sizes, int n_in,
                              void* d_out, int out_size) {
    const float* x   = (const float*)d_in[0];
    const float* wq  = (const float*)d_in[1];
    const float* bq  = (const float*)d_in[2];
    const float* wk  = (const float*)d_in[3];
    const float* bk  = (const float*)d_in[4];
    const float* wv  = (const float*)d_in[5];
    const float* bv  = (const float*)d_in[6];
    const float* wo  = (const float*)d_in[7];
    const float* bo  = (const float*)d_in[8];
    const float* w1  = (const float*)d_in[9];
    const float* b1  = (const float*)d_in[10];
    const float* w2  = (const float*)d_in[11];
    const float* b2  = (const float*)d_in[12];
    const float* g1  = (const float*)d_in[13];
    const float* be1 = (const float*)d_in[14];
    const float* g2  = (const float*)d_in[15];
    const float* be2 = (const float*)d_in[16];
    float* out = (float*)d_out;

    void *p;
    cudaGetSymbolAddress(&p, g_xh);   __half* xh  = (__half*)p;
    cudaGetSymbolAddress(&p, g_xl);   __half* xl  = (__half*)p;
    cudaGetSymbolAddress(&p, g_wqh);  __half* wqh = (__half*)p;
    cudaGetSymbolAddress(&p, g_wql);  __half* wql = (__half*)p;
    cudaGetSymbolAddress(&p, g_wkh);  __half* wkh = (__half*)p;
    cudaGetSymbolAddress(&p, g_wkl);  __half* wkl = (__half*)p;
    cudaGetSymbolAddress(&p, g_wvh);  __half* wvh = (__half*)p;
    cudaGetSymbolAddress(&p, g_woh);  __half* woh = (__half*)p;
    cudaGetSymbolAddress(&p, g_w1h);  __half* w1h = (__half*)p;
    cudaGetSymbolAddress(&p, g_w2h);  __half* w2h = (__half*)p;
    cudaGetSymbolAddress(&p, g_q);    float*  qf  = (float*)p;
    cudaGetSymbolAddress(&p, g_k);    float*  kf  = (float*)p;
    cudaGetSymbolAddress(&p, g_qrh);  __half* qrh = (__half*)p;
    cudaGetSymbolAddress(&p, g_qrl);  __half* qrl = (__half*)p;
    cudaGetSymbolAddress(&p, g_krh);  __half* krh = (__half*)p;
    cudaGetSymbolAddress(&p, g_krl);  __half* krl = (__half*)p;
    cudaGetSymbolAddress(&p, g_vh);   __half* vh  = (__half*)p;
    cudaGetSymbolAddress(&p, g_ctx);  __half* ctx = (__half*)p;
    cudaGetSymbolAddress(&p, g_res1); float*  res1 = (float*)p;
    cudaGetSymbolAddress(&p, g_hbuf); float*  hbuf = (float*)p;
    cudaGetSymbolAddress(&p, g_hh);   __half* hh  = (__half*)p;
    cudaGetSymbolAddress(&p, g_ff1);  __half* ff1 = (__half*)p;
    cudaGetSymbolAddress(&p, g_res2); float*  res2 = (float*)p;

    cudaFuncSetAttribute(gemm_h<false, false, false, true>,
                         cudaFuncAttributeMaxDynamicSharedMemorySize, GH_SMEM);
    cudaFuncSetAttribute(gemm_h<false, true, true, false>,
                         cudaFuncAttributeMaxDynamicSharedMemorySize, GH_SMEM);
    cudaFuncSetAttribute(gemm_h<true, false, false, true>,
                         cudaFuncAttributeMaxDynamicSharedMemorySize, GH_SMEM);
    cudaFuncSetAttribute(gemm_split,
                         cudaFuncAttributeMaxDynamicSharedMemorySize, GS_SMEM);
    cudaFuncSetAttribute(attn_kernel,
                         cudaFuncAttributeMaxDynamicSharedMemorySize, ATT_SMEM);

    // conversions
    launch_f2h_split(x,  xh,  xl,  ROWS * DMODEL);
    launch_f2h_split(wq, wqh, wql, DMODEL * DMODEL);
    launch_f2h_split(wk, wkh, wkl, DMODEL * DMODEL);
    launch_f2h(wv, wvh, DMODEL * DMODEL);
    launch_f2h(wo, woh, DMODEL * DMODEL);
    launch_f2h(w1, w1h, DMODEL * DFF);
    launch_f2h(w2, w2h, DFF * DMODEL);

    dim3 grid1(DMODEL / 128, ROWS / 128);   // (8, 64)
    dim3 gridF(DFF / 128,    ROWS / 128);   // (32, 64)

    // Q,K projections (fp32-accurate split GEMM, fp32 out), V plain fp16
    gemm_split<<<grid1, 256, GS_SMEM>>>(xh, xl, wqh, wql, bq, qf, ROWS, DMODEL, DMODEL);
    gemm_split<<<grid1, 256, GS_SMEM>>>(xh, xl, wkh, wkl, bk, kf, ROWS, DMODEL, DMODEL);
    gemm_h<false, false, false, true><<<grid1, 256, GH_SMEM>>>(xh, wvh, bv, nullptr, nullptr, vh, ROWS, DMODEL, DMODEL);

    // "RoPE" (raw-angle multiply, q scaled by 1/sqrt(Dh)) + hi/lo split
    rope_kernel<<<ROWS, 256>>>(qf, kf, qrh, qrl, krh, krl);

    // attention (split-fp16 QK^T)
    attn_kernel<<<dim3(SEQ / 128, NHEADS, BATCH), 256, ATT_SMEM>>>(qrh, qrl, krh, krl, vh, ctx);

    // output projection + residual(x)
    gemm_h<false, true, true, false><<<grid1, 256, GH_SMEM>>>(ctx, woh, bo, x, res1, nullptr, ROWS, DMODEL, DMODEL);

    // LN1 -> h (fp32 + fp16)
    ln_kernel<<<ROWS, 256>>>(res1, g1, be1, hbuf, hh);

    // FFN
    gemm_h<true,  false, false, true ><<<gridF, 256, GH_SMEM>>>(hh, w1h, b1, nullptr, nullptr, ff1, ROWS, DFF, DMODEL);
    gemm_h<false, true,  true,  false><<<grid1, 256, GH_SMEM>>>(ff1, w2h, b2, hbuf, res2, nullptr, ROWS, DMODEL, DFF);

    // LN2 -> output
    ln_kernel<<<ROWS, 256>>>(res2, g2, be2, out, nullptr);
}

// round 9
// speedup vs baseline: 1.0367x; 1.0367x over previous
#include <cuda_runtime.h>
#include <cuda_fp16.h>
#include <mma.h>
#include <cstdint>

using namespace nvcuda;

// ---------------------------------------------------------------------------
#define BATCH 4
#define SEQ 2048
#define ROWS (BATCH * SEQ)       // 8192
#define DMODEL 1024
#define NHEADS 16
#define DHEAD 64
#define DFF 4096

// ---------------------------------------------------------------------------
// Scratch (static device globals; no allocation allowed)
// ---------------------------------------------------------------------------
__device__ __half g_xh[ROWS * DMODEL];
__device__ __half g_xl[ROWS * DMODEL];
__device__ __half g_wqh[DMODEL * DMODEL];
__device__ __half g_wql[DMODEL * DMODEL];
__device__ __half g_wkh[DMODEL * DMODEL];
__device__ __half g_wkl[DMODEL * DMODEL];
__device__ __half g_wvh[DMODEL * DMODEL];
__device__ __half g_woh[DMODEL * DMODEL];
__device__ __half g_w1h[DMODEL * DFF];
__device__ __half g_w2h[DFF * DMODEL];

__device__ float  g_q[ROWS * DMODEL];
__device__ float  g_k[ROWS * DMODEL];
__device__ __half g_qrh[ROWS * DMODEL];
__device__ __half g_qrl[ROWS * DMODEL];
__device__ __half g_krh[ROWS * DMODEL];
__device__ __half g_krl[ROWS * DMODEL];
__device__ __half g_vh[ROWS * DMODEL];
__device__ __half g_ctx[ROWS * DMODEL];
__device__ float  g_res1[ROWS * DMODEL];
__device__ float  g_hbuf[ROWS * DMODEL];
__device__ __half g_hh[ROWS * DMODEL];
__device__ __half g_ff1[ROWS * DFF];
__device__ float  g_res2[ROWS * DMODEL];

// ---------------------------------------------------------------------------
// cp.async helpers
// ---------------------------------------------------------------------------
__device__ __forceinline__ void cp16(void* s, const void* g) {
    unsigned int sa = (unsigned int)__cvta_generic_to_shared(s);
    asm volatile("cp.async.cg.shared.global [%0], [%1], 16;\n" :: "r"(sa), "l"(g) : "memory");
}
__device__ __forceinline__ void cp_commit() {
    asm volatile("cp.async.commit_group;\n" ::: "memory");
}
template<int N> __device__ __forceinline__ void cp_wait() {
    asm volatile("cp.async.wait_group %0;\n" :: "n"(N) : "memory");
}

// ---------------------------------------------------------------------------
// Fused conversion kernel: all fp32->fp16 (plain + hi/lo split) in ONE launch.
// Region-dispatched by float4 group index. Per-element math identical to the
// previous f2h / f2h_split kernels.
// ---------------------------------------------------------------------------
#define X4  (ROWS * DMODEL / 4)          // 2097152
#define W4  (DMODEL * DMODEL / 4)        // 262144
#define F4  (DMODEL * DFF / 4)           // 1048576
#define CV_B0 X4
#define CV_B1 (CV_B0 + W4)
#define CV_B2 (CV_B1 + W4)
#define CV_B3 (CV_B2 + W4)
#define CV_B4 (CV_B3 + W4)
#define CV_B5 (CV_B4 + F4)
#define CV_B6 (CV_B5 + F4)               // 5242880 total groups

__device__ __forceinline__ void cv_split(const float* __restrict__ in,
                                         __half* __restrict__ hi,
                                         __half* __restrict__ lo, int i) {
    float4 v = ((const float4*)in)[i];
    __half hx = __float2half(v.x), hy = __float2half(v.y);
    __half hz = __float2half(v.z), hw = __float2half(v.w);
    ((__half2*)hi)[2 * i]     = __halves2half2(hx, hy);
    ((__half2*)hi)[2 * i + 1] = __halves2half2(hz, hw);
    ((__half2*)lo)[2 * i]     = __floats2half2_rn(v.x - __half2float(hx),
                                                  v.y - __half2float(hy));
    ((__half2*)lo)[2 * i + 1] = __floats2half2_rn(v.z - __half2float(hz),
                                                  v.w - __half2float(hw));
}
__device__ __forceinline__ void cv_plain(const float* __restrict__ in,
                                         __half* __restrict__ out, int i) {
    float4 v = ((const float4*)in)[i];
    ((__half2*)out)[2 * i]     = __floats2half2_rn(v.x, v.y);
    ((__half2*)out)[2 * i + 1] = __floats2half2_rn(v.z, v.w);
}

__global__ void __launch_bounds__(256) conv_all(
    const float* __restrict__ x,  const float* __restrict__ wq,
    const float* __restrict__ wk, const float* __restrict__ wv,
    const float* __restrict__ wo, const float* __restrict__ w1,
    const float* __restrict__ w2,
    __half* __restrict__ xh,  __half* __restrict__ xl,
    __half* __restrict__ wqh, __half* __restrict__ wql,
    __half* __restrict__ wkh, __half* __restrict__ wkl,
    __half* __restrict__ wvh, __half* __restrict__ woh,
    __half* __restrict__ w1h, __half* __restrict__ w2h)
{
    int i = blockIdx.x * 256 + threadIdx.x;
    if (i < CV_B0)      cv_split(x,  xh,  xl,  i);
    else if (i < CV_B1) cv_split(wq, wqh, wql, i - CV_B0);
    else if (i < CV_B2) cv_split(wk, wkh, wkl, i - CV_B1);
    else if (i < CV_B3) cv_plain(wv, wvh, i - CV_B2);
    else if (i < CV_B4) cv_plain(wo, woh, i - CV_B3);
    else if (i < CV_B5) cv_plain(w1, w1h, i - CV_B4);
    else if (i < CV_B6) cv_plain(w2, w2h, i - CV_B5);
}

// ---------------------------------------------------------------------------
// Plain fp16 GEMM, 128x128 tiles, BK=64, cp.async 2-stage single-barrier
// pipeline. 256 threads = 8 warps (4x2), warp tile 32x64.
// Stage = A 128x72 halfs (18432B) + B 64x136 halfs (17408B) = 35840B; x2 = 71680.
// ---------------------------------------------------------------------------
#define GH_STAGE_H 17920
#define GH_SMEM 71680

template<bool RELU, bool RESID, bool WF32, bool WF16>
__global__ void __launch_bounds__(256) gemm_h(
    const __half* __restrict__ A, const __half* __restrict__ Bw,
    const float* __restrict__ bias, const float* __restrict__ resid,
    float* __restrict__ Cf, __half* __restrict__ Ch,
    int M, int N, int K)
{
    extern __shared__ __align__(16) unsigned char sm[];
    __half* SH = (__half*)sm;

    const int tid = threadIdx.x;
    const int warp = tid >> 5;
    const int wm = warp >> 1;
    const int wn = warp & 1;
    const int row0 = blockIdx.y * 128;
    const int col0 = blockIdx.x * 128;

    wmma::fragment<wmma::accumulator, 16, 16, 16, float> acc[2][4];
#pragma unroll
    for (int i = 0; i < 2; i++)
#pragma unroll
        for (int j = 0; j < 4; j++) wmma::fill_fragment(acc[i][j], 0.f);

    auto load_stage = [&](int k0, int s) {
        __half* As = SH + s * GH_STAGE_H;
        __half* Bs = As + 9216;
#pragma unroll
        for (int i = 0; i < 4; i++) {          // A: 128x64 -> 1024 chunks
            int c = tid + i * 256;
            int r = c >> 3, q = c & 7;
            cp16(As + r * 72 + q * 8, A + (size_t)(row0 + r) * K + k0 + q * 8);
        }
#pragma unroll
        for (int i = 0; i < 4; i++) {          // B: 64x128 -> 1024 chunks
            int c = tid + i * 256;
            int r = c >> 4, q = c & 15;
            cp16(Bs + r * 136 + q * 8, Bw + (size_t)(k0 + r) * N + col0 + q * 8);
        }
    };

    const int nk = K >> 6;
    load_stage(0, 0); cp_commit();
    for (int kt = 0; kt < nk; kt++) {
        cp_wait<0>();
        __syncthreads();
        if (kt + 1 < nk) { load_stage((kt + 1) << 6, (kt + 1) & 1); cp_commit(); }
        __half* As = SH + (kt & 1) * GH_STAGE_H;
        __half* Bs = As + 9216;
#pragma unroll
        for (int kk = 0; kk < 4; kk++) {
            wmma::fragment<wmma::matrix_a, 16, 16, 16, __half, wmma::row_major> af[2];
            wmma::fragment<wmma::matrix_b, 16, 16, 16, __half, wmma::row_major> bf[4];
#pragma unroll
            for (int i = 0; i < 2; i++)
                wmma::load_matrix_sync(af[i], As + (wm * 32 + i * 16) * 72 + kk * 16, 72);
#pragma unroll
            for (int j = 0; j < 4; j++)
                wmma::load_matrix_sync(bf[j], Bs + (kk * 16) * 136 + wn * 64 + j * 16, 136);
#pragma unroll
            for (int i = 0; i < 2; i++)
#pragma unroll
                for (int j = 0; j < 4; j++)
                    wmma::mma_sync(acc[i][j], af[i], bf[j], acc[i][j]);
        }
    }
    __syncthreads();

    float* stg = (float*)sm;
#pragma unroll
    for (int i = 0; i < 2; i++)
#pragma unroll
        for (int j = 0; j < 4; j++)
            wmma::store_matrix_sync(stg + (wm * 32 + i * 16) * 132 + wn * 64 + j * 16,
                                    acc[i][j], 132, wmma::mem_row_major);
    __syncthreads();

#pragma unroll
    for (int e = 0; e < 16; e++) {
        int idx = tid + e * 256;
        int r = idx >> 5, c4 = idx & 31;
        float4 v = *(float4*)(stg + r * 132 + c4 * 4);
        float4 bb = *(const float4*)(bias + col0 + c4 * 4);
        v.x += bb.x; v.y += bb.y; v.z += bb.z; v.w += bb.w;
        if (RELU) { v.x = fmaxf(v.x, 0.f); v.y = fmaxf(v.y, 0.f); v.z = fmaxf(v.z, 0.f); v.w = fmaxf(v.w, 0.f); }
        size_t g = (size_t)(row0 + r) * N + col0 + c4 * 4;
        if (RESID) {
            float4 rr = *(const float4*)(resid + g);
            v.x += rr.x; v.y += rr.y; v.z += rr.z; v.w += rr.w;
        }
        if (WF32) *(float4*)(Cf + g) = v;
        if (WF16) {
            ((__half2*)(Ch + g))[0] = __floats2half2_rn(v.x, v.y);
            ((__half2*)(Ch + g))[1] = __floats2half2_rn(v.z, v.w);
        }
    }
}

// ---------------------------------------------------------------------------
// Split-fp16 GEMM (fp32-accurate), BK=32 2-stage single-barrier, fp32 out.
// ---------------------------------------------------------------------------
#define GS_STAGE_H 20992
#define GS_SMEM 83968

__global__ void __launch_bounds__(256) gemm_split(
    const __half* __restrict__ Ah_, const __half* __restrict__ Al_,
    const __half* __restrict__ Bh_, const __half* __restrict__ Bl_,
    const float* __restrict__ bias, float* __restrict__ Cf,
    int M, int N, int K)
{
    extern __shared__ __align__(16) unsigned char sm[];
    __half* SH = (__half*)sm;

    const int tid = threadIdx.x;
    const int warp = tid >> 5;
    const int wm = warp >> 1;
    const int wn = warp & 1;
    const int row0 = blockIdx.y * 128;
    const int col0 = blockIdx.x * 128;

    wmma::fragment<wmma::accumulator, 16, 16, 16, float> acc[2][4];
#pragma unroll
    for (int i = 0; i < 2; i++)
#pragma unroll
        for (int j = 0; j < 4; j++) wmma::fill_fragment(acc[i][j], 0.f);

    auto load_stage = [&](int k0, int s) {
        __half* Ahs = SH + s * GS_STAGE_H;
        __half* Als = Ahs + 6144;
        __half* Bhs = Als + 6144;
        __half* Bls = Bhs + 4352;
#pragma unroll
        for (int i = 0; i < 2; i++) {
            int c = tid + i * 256;
            int r = c >> 2, q = c & 3;
            size_t g = (size_t)(row0 + r) * K + k0 + q * 8;
            cp16(Ahs + r * 48 + q * 8, Ah_ + g);
            cp16(Als + r * 48 + q * 8, Al_ + g);
        }
#pragma unroll
        for (int i = 0; i < 2; i++) {
            int c = tid + i * 256;
            int r = c >> 4, q = c & 15;
            size_t g = (size_t)(k0 + r) * N + col0 + q * 8;
            cp16(Bhs + r * 136 + q * 8, Bh_ + g);
            cp16(Bls + r * 136 + q * 8, Bl_ + g);
        }
    };

    const int nk = K >> 5;
    load_stage(0, 0); cp_commit();
    for (int kt = 0; kt < nk; kt++) {
        cp_wait<0>();
        __syncthreads();
        if (kt + 1 < nk) { load_stage((kt + 1) << 5, (kt + 1) & 1); cp_commit(); }
        __half* Ahs = SH + (kt & 1) * GS_STAGE_H;
        __half* Als = Ahs + 6144;
        __half* Bhs = Als + 6144;
        __half* Bls = Bhs + 4352;
#pragma unroll
        for (int kk = 0; kk < 2; kk++) {
            wmma::fragment<wmma::matrix_a, 16, 16, 16, __half, wmma::row_major> afh[2], afl[2];
            wmma::fragment<wmma::matrix_b, 16, 16, 16, __half, wmma::row_major> bfh[4], bfl[4];
#pragma unroll
            for (int i = 0; i < 2; i++) {
                wmma::load_matrix_sync(afh[i], Ahs + (wm * 32 + i * 16) * 48 + kk * 16, 48);
                wmma::load_matrix_sync(afl[i], Als + (wm * 32 + i * 16) * 48 + kk * 16, 48);
            }
#pragma unroll
            for (int j = 0; j < 4; j++) {
                wmma::load_matrix_sync(bfh[j], Bhs + (kk * 16) * 136 + wn * 64 + j * 16, 136);
                wmma::load_matrix_sync(bfl[j], Bls + (kk * 16) * 136 + wn * 64 + j * 16, 136);
            }
#pragma unroll
            for (int i = 0; i < 2; i++)
#pragma unroll
                for (int j = 0; j < 4; j++) {
                    wmma::mma_sync(acc[i][j], afh[i], bfh[j], acc[i][j]);
                    wmma::mma_sync(acc[i][j], afh[i], bfl[j], acc[i][j]);
                    wmma::mma_sync(acc[i][j], afl[i], bfh[j], acc[i][j]);
                }
        }
    }
    __syncthreads();

    float* stg = (float*)sm;
#pragma unroll
    for (int i = 0; i < 2; i++)
#pragma unroll
        for (int j = 0; j < 4; j++)
            wmma::store_matrix_sync(stg + (wm * 32 + i * 16) * 132 + wn * 64 + j * 16,
                                    acc[i][j], 132, wmma::mem_row_major);
    __syncthreads();

#pragma unroll
    for (int e = 0; e < 16; e++) {
        int idx = tid + e * 256;
        int r = idx >> 5, c4 = idx & 31;
        float4 v = *(float4*)(stg + r * 132 + c4 * 4);
        float4 bb = *(const float4*)(bias + col0 + c4 * 4);
        v.x += bb.x; v.y += bb.y; v.z += bb.z; v.w += bb.w;
        *(float4*)(Cf + (size_t)(row0 + r) * N + col0 + c4 * 4) = v;
    }
}

// ---------------------------------------------------------------------------
// "RoPE" exactly as the reference defines it: multiply by the raw ANGLES
// (no cos/sin). q pre-scaled by 1/sqrt(Dh). Outputs hi/lo fp16 splits.
// ---------------------------------------------------------------------------
__global__ void __launch_bounds__(256) rope_kernel(
    const float* __restrict__ q, const float* __restrict__ k,
    __half* __restrict__ qrh, __half* __restrict__ qrl,
    __half* __restrict__ krh, __half* __restrict__ krl)
{
    __shared__ float sInv[32];
    int tid = threadIdx.x;
    if (tid < 32)
        sInv[tid] = (float)exp(-0.28782313662425575 * (double)tid); // ln(1e4)/32
    __syncthreads();

    int row = blockIdx.x;
    int s = row & (SEQ - 1);
    float fs = (float)s;

#pragma unroll
    for (int t = 0; t < 2; t++) {
        int idx = tid + t * 256;        // 0..511
        int head = idx >> 5;
        int j = idx & 31;
        int base = row * DMODEL + head * DHEAD;

        float t0 = q[base + 2 * j];
        float t1 = q[base + 2 * j + 1];
        float u0 = k[base + 2 * j];
        float u1 = k[base + 2 * j + 1];

        int ic = (2 * j < 32) ? 2 * j : 2 * j - 32;
        int is = (2 * j + 1 < 32) ? 2 * j + 1 : 2 * j - 31;
        float c  = fs * sInv[ic];   // raw angle, NOT cos
        float si = fs * sInv[is];   // raw angle, NOT sin

        float o0 = (t0 * c - t1 * si) * 0.125f;
        float o1 = (t0 * si + t1 * c) * 0.125f;
        __half h0 = __float2half(o0);
        __half h1 = __float2half(o1);
        qrh[base + j]      = h0;
        qrh[base + 32 + j] = h1;
        qrl[base + j]      = __float2half(o0 - __half2float(h0));
        qrl[base + 32 + j] = __float2half(o1 - __half2float(h1));

        float p0 = u0 * c - u1 * si;
        float p1 = u0 * si + u1 * c;
        __half g0 = __float2half(p0);
        __half g1 = __float2half(p1);
        krh[base + j]      = g0;
        krh[base + 32 + j] = g1;
        krl[base + j]      = __float2half(p0 - __half2float(g0));
        krl[base + 32 + j] = __float2half(p1 - __half2float(g1));
    }
}

// ---------------------------------------------------------------------------
// Flash attention (round-5 proven config): grid (S/64, H, B), 128 threads
// (4 warps, 16 q-rows each). kh/kl/v 64x64 tiles staged in smem (cp.async,
// double-buffered). Split-fp16 QK^T (3 MMAs). 2 CTAs/SM.
// ---------------------------------------------------------------------------
#define ATT_SMEM 99840

__global__ void __launch_bounds__(128) attn_kernel(
    const __half* __restrict__ qh, const __half* __restrict__ ql,
    const __half* __restrict__ kh, const __half* __restrict__ kl,
    const __half* __restrict__ v, __half* __restrict__ ctx)
{
    extern __shared__ __align__(16) unsigned char sm[];
    __half* KH = (__half*)sm;                 // [2][64][72]
    __half* KL = KH + 9216;
    __half* VT = KL + 9216;
    float*  sS = (float*)(sm + 55296);        // [4][16][68]
    __half* sP = (__half*)(sm + 72704);       // [4][16][72]
    float*  sO = (float*)(sm + 81920);        // [4][16][68]
    float*  sM = (float*)(sm + 99328);
    float*  sL = sM + 64;

    const int tid = threadIdx.x;
    const int w = tid >> 5;
    const int lane = tid & 31;
    const int qt = blockIdx.x;
    const int h = blockIdx.y;
    const int b = blockIdx.z;
    const int hc = h * DHEAD;
    const int brow = b * SEQ;
    const int qrow0 = brow + qt * 64 + w * 16;

    const int r = lane >> 1;
    const int half = lane & 1;

    if (half == 0) { sM[w * 16 + r] = -1e30f; sL[w * 16 + r] = 0.f; }
    {
        float* Orow = sO + (w * 16 + r) * 68 + half * 32;
#pragma unroll
        for (int c = 0; c < 32; c++) Orow[c] = 0.f;
    }

    wmma::fragment<wmma::matrix_a, 16, 16, 16, __half, wmma::row_major> qfh[4], qfl[4];
#pragma unroll
    for (int kk = 0; kk < 4; kk++) {
        wmma::load_matrix_sync(qfh[kk], qh + (size_t)qrow0 * DMODEL + hc + kk * 16, DMODEL);
        wmma::load_matrix_sync(qfl[kk], ql + (size_t)qrow0 * DMODEL + hc + kk * 16, DMODEL);
    }

    auto load_stage = [&](int kv, int s) {
#pragma unroll
        for (int i = 0; i < 4; i++) {
            int c = tid + i * 128;
            int rr = c >> 3, qq = c & 7;
            size_t g = (size_t)(brow + kv * 64 + rr) * DMODEL + hc + qq * 8;
            int so = s * 4608 + rr * 72 + qq * 8;
            cp16(KH + so, kh + g);
            cp16(KL + so, kl + g);
            cp16(VT + so, v + g);
        }
    };

    load_stage(0, 0); cp_commit();

    for (int kt = 0; kt < SEQ / 64; kt++) {
        if (kt + 1 < SEQ / 64) { load_stage(kt + 1, (kt + 1) & 1); cp_commit(); cp_wait<1>(); }
        else cp_wait<0>();
        __syncthreads();

        const int s = kt & 1;
        __half* KHs = KH + s * 4608;
        __half* KLs = KL + s * 4608;
        __half* VTs = VT + s * 4608;

        // ---- S = Q @ K^T (split: qh*kh + qh*kl + ql*kh) ----
#pragma unroll
        for (int kc = 0; kc < 4; kc++) {
            wmma::fragment<wmma::accumulator, 16, 16, 16, float> sacc;
            wmma::fill_fragment(sacc, 0.f);
#pragma unroll
            for (int kk = 0; kk < 4; kk++) {
                wmma::fragment<wmma::matrix_b, 16, 16, 16, __half, wmma::col_major> bfh, bfl;
                wmma::load_matrix_sync(bfh, KHs + (kc * 16) * 72 + kk * 16, 72);
                wmma::load_matrix_sync(bfl, KLs + (kc * 16) * 72 + kk * 16, 72);
                wmma::mma_sync(sacc, qfh[kk], bfh, sacc);
                wmma::mma_sync(sacc, qfh[kk], bfl, sacc);
                wmma::mma_sync(sacc, qfl[kk], bfh, sacc);
            }
            wmma::store_matrix_sync(sS + (w * 16) * 68 + kc * 16, sacc, 68, wmma::mem_row_major);
        }
        __syncwarp();

        // ---- online softmax (lane pairs split the 64 cols) ----
        {
            float* Srow = sS + (w * 16 + r) * 68 + half * 32;
            float mo = sM[w * 16 + r];
            float mt = -1e30f;
#pragma unroll
            for (int c = 0; c < 32; c++) mt = fmaxf(mt, Srow[c]);
            mt = fmaxf(mt, __shfl_xor_sync(0xffffffffu, mt, 1));
            float mn = fmaxf(mo, mt);
            float alpha = __expf(mo - mn);
            float sum = 0.f;
            __half* Prow = sP + (w * 16 + r) * 72 + half * 32;
#pragma unroll
            for (int c = 0; c < 32; c++) {
                float p = __expf(Srow[c] - mn);
                Prow[c] = __float2half(p);
                sum += p;
            }
            sum += __shfl_xor_sync(0xffffffffu, sum, 1);
            if (half == 0) {
                sL[w * 16 + r] = sL[w * 16 + r] * alpha + sum;
                sM[w * 16 + r] = mn;
            }
            float* Orow = sO + (w * 16 + r) * 68 + half * 32;
#pragma unroll
            for (int c = 0; c < 32; c++) Orow[c] *= alpha;
        }
        __syncwarp();

        // ---- O += P @ V ----
#pragma unroll
        for (int dc = 0; dc < 4; dc++) {
            wmma::fragment<wmma::accumulator, 16, 16, 16, float> oacc;
            wmma::load_matrix_sync(oacc, sO + (w * 16) * 68 + dc * 16, 68, wmma::mem_row_major);
#pragma unroll
            for (int kk = 0; kk < 4; kk++) {
                wmma::fragment<wmma::matrix_a, 16, 16, 16, __half, wmma::row_major> pf;
                wmma::load_matrix_sync(pf, sP + (w * 16) * 72 + kk * 16, 72);
                wmma::fragment<wmma::matrix_b, 16, 16, 16, __half, wmma::row_major> vf;
                wmma::load_matrix_sync(vf, VTs + (kk * 16) * 72 + dc * 16, 72);
                wmma::mma_sync(oacc, pf, vf, oacc);
            }
            wmma::store_matrix_sync(sO + (w * 16) * 68 + dc * 16, oacc, 68, wmma::mem_row_major);
        }
        __syncthreads();   // all warps done with this stage's tiles
    }

    // ---- epilogue: O / l ----
    {
        float inv = 1.f / sL[w * 16 + r];
        float* Orow = sO + (w * 16 + r) * 68 + half * 32;
        __half* dst = ctx + (size_t)(qrow0 + r) * DMODEL + hc + half * 32;
#pragma unroll
        for (int c = 0; c < 32; c++) dst[c] = __float2half(Orow[c] * inv);
    }
}

// ---------------------------------------------------------------------------
// LayerNorm over 1024 cols, block=256, one row per block. Optional fp16 copy.
// ---------------------------------------------------------------------------
__global__ void __launch_bounds__(256) ln_kernel(
    const float* __restrict__ in, const float* __restrict__ g,
    const float* __restrict__ be, float* __restrict__ outf,
    __half* __restrict__ outh)
{
    int row = blockIdx.x;
    int tid = threadIdx.x;
    float4 v = ((const float4*)(in + (size_t)row * DMODEL))[tid];
    float s  = v.x + v.y + v.z + v.w;
    float ss = v.x * v.x + v.y * v.y + v.z * v.z + v.w * v.w;
#pragma unroll
    for (int o = 16; o > 0; o >>= 1) {
        s  += __shfl_down_sync(0xffffffffu, s, o);
        ss += __shfl_down_sync(0xffffffffu, ss, o);
    }
    __shared__ float shs[8], shss[8], smu, srs;
    int lane = tid & 31, wid = tid >> 5;
    if (lane == 0) { shs[wid] = s; shss[wid] = ss; }
    __syncthreads();
    if (tid == 0) {
        float S = 0.f, SS = 0.f;
#pragma unroll
        for (int i = 0; i < 8; i++) { S += shs[i]; SS += shss[i]; }
        float mu = S * (1.f / 1024.f);
        float var = SS * (1.f / 1024.f) - mu * mu;
        smu = mu;
        srs = rsqrtf(var + 1e-5f);
    }
    __syncthreads();
    float mu = smu, rs = srs;
    float4 gv = ((const float4*)g)[tid];
    float4 bv = ((const float4*)be)[tid];
    float4 o;
    o.x = (v.x - mu) * rs * gv.x + bv.x;
    o.y = (v.y - mu) * rs * gv.y + bv.y;
    o.z = (v.z - mu) * rs * gv.z + bv.z;
    o.w = (v.w - mu) * rs * gv.w + bv.w;
    ((float4*)(outf + (size_t)row * DMODEL))[tid] = o;
    if (outh) {
        ((__half2*)(outh + (size_t)row * DMODEL))[2 * tid]     = __floats2half2_rn(o.x, o.y);
        ((__half2*)(outh + (size_t)row * DMODEL))[2 * tid + 1] = __floats2half2_rn(o.z, o.w);
    }
}

extern "C" void kernel_launch(void* const* d_in, const int* in_sizes, int n_in,
                              void* d_out, int out_size) {
    const float* x   = (const float*)d_in[0];
    const float* wq  = (const float*)d_in[1];
    const float* bq  = (const float*)d_in[2];
    const float* wk  = (const float*)d_in[3];
    const float* bk  = (const float*)d_in[4];
    const float* wv  = (const float*)d_in[5];
    const float* bv  = (const float*)d_in[6];
    const float* wo  = (const float*)d_in[7];
    const float* bo  = (const float*)d_in[8];
    const float* w1  = (const float*)d_in[9];
    const float* b1  = (const float*)d_in[10];
    const float* w2  = (const float*)d_in[11];
    const float* b2  = (const float*)d_in[12];
    const float* g1  = (const float*)d_in[13];
    const float* be1 = (const float*)d_in[14];
    const float* g2  = (const float*)d_in[15];
    const float* be2 = (const float*)d_in[16];
    float* out = (float*)d_out;

    void *p;
    cudaGetSymbolAddress(&p, g_xh);   __half* xh  = (__half*)p;
    cudaGetSymbolAddress(&p, g_xl);   __half* xl  = (__half*)p;
    cudaGetSymbolAddress(&p, g_wqh);  __half* wqh = (__half*)p;
    cudaGetSymbolAddress(&p, g_wql);  __half* wql = (__half*)p;
    cudaGetSymbolAddress(&p, g_wkh);  __half* wkh = (__half*)p;
    cudaGetSymbolAddress(&p, g_wkl);  __half* wkl = (__half*)p;
    cudaGetSymbolAddress(&p, g_wvh);  __half* wvh = (__half*)p;
    cudaGetSymbolAddress(&p, g_woh);  __half* woh = (__half*)p;
    cudaGetSymbolAddress(&p, g_w1h);  __half* w1h = (__half*)p;
    cudaGetSymbolAddress(&p, g_w2h);  __half* w2h = (__half*)p;
    cudaGetSymbolAddress(&p, g_q);    float*  qf  = (float*)p;
    cudaGetSymbolAddress(&p, g_k);    float*  kf  = (float*)p;
    cudaGetSymbolAddress(&p, g_qrh);  __half* qrh = (__half*)p;
    cudaGetSymbolAddress(&p, g_qrl);  __half* qrl = (__half*)p;
    cudaGetSymbolAddress(&p, g_krh);  __half* krh = (__half*)p;
    cudaGetSymbolAddress(&p, g_krl);  __half* krl = (__half*)p;
    cudaGetSymbolAddress(&p, g_vh);   __half* vh  = (__half*)p;
    cudaGetSymbolAddress(&p, g_ctx);  __half* ctx = (__half*)p;
    cudaGetSymbolAddress(&p, g_res1); float*  res1 = (float*)p;
    cudaGetSymbolAddress(&p, g_hbuf); float*  hbuf = (float*)p;
    cudaGetSymbolAddress(&p, g_hh);   __half* hh  = (__half*)p;
    cudaGetSymbolAddress(&p, g_ff1);  __half* ff1 = (__half*)p;
    cudaGetSymbolAddress(&p, g_res2); float*  res2 = (float*)p;

    cudaFuncSetAttribute(gemm_h<false, false, false, true>,
                         cudaFuncAttributeMaxDynamicSharedMemorySize, GH_SMEM);
    cudaFuncSetAttribute(gemm_h<false, true, true, false>,
                         cudaFuncAttributeMaxDynamicSharedMemorySize, GH_SMEM);
    cudaFuncSetAttribute(gemm_h<true, false, false, true>,
                         cudaFuncAttributeMaxDynamicSharedMemorySize, GH_SMEM);
    cudaFuncSetAttribute(gemm_split,
                         cudaFuncAttributeMaxDynamicSharedMemorySize, GS_SMEM);
    cudaFuncSetAttribute(attn_kernel,
                         cudaFuncAttributeMaxDynamicSharedMemorySize, ATT_SMEM);

    // launch 0: all conversions fused
    conv_all<<<CV_B6 / 256, 256>>>(x, wq, wk, wv, wo, w1, w2,
                                   xh, xl, wqh, wql, wkh, wkl, wvh, woh, w1h, w2h);

    dim3 grid1(DMODEL / 128, ROWS / 128);   // (8, 64)
    dim3 gridF(DFF / 128,    ROWS / 128);   // (32, 64)

    // launches 1-3: Q,K split projections (fp32 out), V plain fp16
    gemm_split<<<grid1, 256, GS_SMEM>>>(xh, xl, wqh, wql, bq, qf, ROWS, DMODEL, DMODEL);
    gemm_split<<<grid1, 256, GS_SMEM>>>(xh, xl, wkh, wkl, bk, kf, ROWS, DMODEL, DMODEL);
    gemm_h<false, false, false, true><<<grid1, 256, GH_SMEM>>>(xh, wvh, bv, nullptr, nullptr, vh, ROWS, DMODEL, DMODEL);

    // launch 4: "RoPE" (raw-angle multiply, q scaled by 1/sqrt(Dh)) + hi/lo split
    rope_kernel<<<ROWS, 256>>>(qf, kf, qrh, qrl, krh, krl);

    // launch 5: attention  (ncu -s 5 -c 1 captures THIS kernel)
    attn_kernel<<<dim3(SEQ / 64, NHEADS, BATCH), 128, ATT_SMEM>>>(qrh, qrl, krh, krl, vh, ctx);

    // output projection + residual(x)
    gemm_h<false, true, true, false><<<grid1, 256, GH_SMEM>>>(ctx, woh, bo, x, res1, nullptr, ROWS, DMODEL, DMODEL);

    // LN1 -> h (fp32 + fp16)
    ln_kernel<<<ROWS, 256>>>(res1, g1, be1, hbuf, hh);

    // FFN
    gemm_h<true,  false, false, true ><<<gridF, 256, GH_SMEM>>>(hh, w1h, b1, nullptr, nullptr, ff1, ROWS, DFF, DMODEL);
    gemm_h<false, true,  true,  false><<<grid1, 256, GH_SMEM>>>(ff1, w2h, b2, hbuf, res2, nullptr, ROWS, DMODEL, DFF);

    // LN2 -> output
    ln_kernel<<<ROWS, 256>>>(res2, g2, be2, out, nullptr);
}

// round 10
// speedup vs baseline: 1.4309x; 1.3803x over previous
#include <cuda_runtime.h>
#include <cuda_fp16.h>
#include <mma.h>
#include <cstdint>

using namespace nvcuda;

// ---------------------------------------------------------------------------
#define BATCH 4
#define SEQ 2048
#define ROWS (BATCH * SEQ)       // 8192
#define DMODEL 1024
#define NHEADS 16
#define DHEAD 64
#define DFF 4096

// ---------------------------------------------------------------------------
// Scratch (static device globals; no allocation allowed)
// ---------------------------------------------------------------------------
__device__ __half g_xh[ROWS * DMODEL];
__device__ __half g_xl[ROWS * DMODEL];
__device__ __half g_wqh[DMODEL * DMODEL];
__device__ __half g_wql[DMODEL * DMODEL];
__device__ __half g_wkh[DMODEL * DMODEL];
__device__ __half g_wkl[DMODEL * DMODEL];
__device__ __half g_wvh[DMODEL * DMODEL];
__device__ __half g_woh[DMODEL * DMODEL];
__device__ __half g_w1h[DMODEL * DFF];
__device__ __half g_w2h[DFF * DMODEL];

__device__ __half g_qrh[ROWS * DMODEL];
__device__ __half g_qrl[ROWS * DMODEL];
__device__ __half g_krh[ROWS * DMODEL];
__device__ __half g_krl[ROWS * DMODEL];
__device__ __half g_vh[ROWS * DMODEL];
__device__ __half g_ctx[ROWS * DMODEL];
__device__ float  g_res1[ROWS * DMODEL];
__device__ float  g_hbuf[ROWS * DMODEL];
__device__ __half g_hh[ROWS * DMODEL];
__device__ __half g_ff1[ROWS * DFF];
__device__ float  g_res2[ROWS * DMODEL];

// ---------------------------------------------------------------------------
// cp.async + mma helpers
// ---------------------------------------------------------------------------
__device__ __forceinline__ void cp16(void* s, const void* g) {
    unsigned int sa = (unsigned int)__cvta_generic_to_shared(s);
    asm volatile("cp.async.cg.shared.global [%0], [%1], 16;\n" :: "r"(sa), "l"(g) : "memory");
}
__device__ __forceinline__ void cp_commit() {
    asm volatile("cp.async.commit_group;\n" ::: "memory");
}
template<int N> __device__ __forceinline__ void cp_wait() {
    asm volatile("cp.async.wait_group %0;\n" :: "n"(N) : "memory");
}

__device__ __forceinline__ void mma16816(float* c, const uint32_t* a,
                                         uint32_t b0, uint32_t b1) {
    asm volatile(
        "mma.sync.aligned.m16n8k16.row.col.f32.f16.f16.f32 "
        "{%0,%1,%2,%3}, {%4,%5,%6,%7}, {%8,%9}, {%0,%1,%2,%3};\n"
        : "+f"(c[0]), "+f"(c[1]), "+f"(c[2]), "+f"(c[3])
        : "r"(a[0]), "r"(a[1]), "r"(a[2]), "r"(a[3]), "r"(b0), "r"(b1));
}

__device__ __forceinline__ uint32_t h2u(__half a, __half b) {
    __half2 t = __halves2half2(a, b);
    return *(uint32_t*)&t;
}
__device__ __forceinline__ uint32_t f2u2(float a, float b) {
    __half2 t = __floats2half2_rn(a, b);
    return *(uint32_t*)&t;
}

// ---------------------------------------------------------------------------
// Fused conversion kernel (unchanged from R9)
// ---------------------------------------------------------------------------
#define X4  (ROWS * DMODEL / 4)
#define W4  (DMODEL * DMODEL / 4)
#define F4  (DMODEL * DFF / 4)
#define CV_B0 X4
#define CV_B1 (CV_B0 + W4)
#define CV_B2 (CV_B1 + W4)
#define CV_B3 (CV_B2 + W4)
#define CV_B4 (CV_B3 + W4)
#define CV_B5 (CV_B4 + F4)
#define CV_B6 (CV_B5 + F4)

__device__ __forceinline__ void cv_split(const float* __restrict__ in,
                                         __half* __restrict__ hi,
                                         __half* __restrict__ lo, int i) {
    float4 v = ((const float4*)in)[i];
    __half hx = __float2half(v.x), hy = __float2half(v.y);
    __half hz = __float2half(v.z), hw = __float2half(v.w);
    ((__half2*)hi)[2 * i]     = __halves2half2(hx, hy);
    ((__half2*)hi)[2 * i + 1] = __halves2half2(hz, hw);
    ((__half2*)lo)[2 * i]     = __floats2half2_rn(v.x - __half2float(hx),
                                                  v.y - __half2float(hy));
    ((__half2*)lo)[2 * i + 1] = __floats2half2_rn(v.z - __half2float(hz),
                                                  v.w - __half2float(hw));
}
__device__ __forceinline__ void cv_plain(const float* __restrict__ in,
                                         __half* __restrict__ out, int i) {
    float4 v = ((const float4*)in)[i];
    ((__half2*)out)[2 * i]     = __floats2half2_rn(v.x, v.y);
    ((__half2*)out)[2 * i + 1] = __floats2half2_rn(v.z, v.w);
}

__global__ void __launch_bounds__(256) conv_all(
    const float* __restrict__ x,  const float* __restrict__ wq,
    const float* __restrict__ wk, const float* __restrict__ wv,
    const float* __restrict__ wo, const float* __restrict__ w1,
    const float* __restrict__ w2,
    __half* __restrict__ xh,  __half* __restrict__ xl,
    __half* __restrict__ wqh, __half* __restrict__ wql,
    __half* __restrict__ wkh, __half* __restrict__ wkl,
    __half* __restrict__ wvh, __half* __restrict__ woh,
    __half* __restrict__ w1h, __half* __restrict__ w2h)
{
    int i = blockIdx.x * 256 + threadIdx.x;
    if (i < CV_B0)      cv_split(x,  xh,  xl,  i);
    else if (i < CV_B1) cv_split(wq, wqh, wql, i - CV_B0);
    else if (i < CV_B2) cv_split(wk, wkh, wkl, i - CV_B1);
    else if (i < CV_B3) cv_plain(wv, wvh, i - CV_B2);
    else if (i < CV_B4) cv_plain(wo, woh, i - CV_B3);
    else if (i < CV_B5) cv_plain(w1, w1h, i - CV_B4);
    else if (i < CV_B6) cv_plain(w2, w2h, i - CV_B5);
}

// ---------------------------------------------------------------------------
// Plain fp16 GEMM (R5-proven): 128x128x32 tiles, cp.async 3-stage pipeline,
// one barrier per k-iter. 256 threads = 8 warps (4x2), warp tile 32x64.
// ---------------------------------------------------------------------------
#define GH_STAGE_H 10496
#define GH_SMEM 67584

template<bool RELU, bool RESID, bool WF32, bool WF16>
__global__ void __launch_bounds__(256) gemm_h(
    const __half* __restrict__ A, const __half* __restrict__ Bw,
    const float* __restrict__ bias, const float* __restrict__ resid,
    float* __restrict__ Cf, __half* __restrict__ Ch,
    int M, int N, int K)
{
    extern __shared__ __align__(16) unsigned char sm[];
    __half* SH = (__half*)sm;

    const int tid = threadIdx.x;
    const int warp = tid >> 5;
    const int wm = warp >> 1;
    const int wn = warp & 1;
    const int row0 = blockIdx.y * 128;
    const int col0 = blockIdx.x * 128;

    wmma::fragment<wmma::accumulator, 16, 16, 16, float> acc[2][4];
#pragma unroll
    for (int i = 0; i < 2; i++)
#pragma unroll
        for (int j = 0; j < 4; j++) wmma::fill_fragment(acc[i][j], 0.f);

    auto load_stage = [&](int k0, int s) {
        __half* As = SH + s * GH_STAGE_H;
        __half* Bs = As + 6144;
#pragma unroll
        for (int i = 0; i < 2; i++) {
            int c = tid + i * 256;
            int r = c >> 2, q = c & 3;
            cp16(As + r * 48 + q * 8, A + (size_t)(row0 + r) * K + k0 + q * 8);
        }
#pragma unroll
        for (int i = 0; i < 2; i++) {
            int c = tid + i * 256;
            int r = c >> 4, q = c & 15;
            cp16(Bs + r * 136 + q * 8, Bw + (size_t)(k0 + r) * N + col0 + q * 8);
        }
    };

    const int nk = K >> 5;
    load_stage(0, 0); cp_commit();
    load_stage(32, 1); cp_commit();
    for (int kt = 0; kt < nk; kt++) {
        if (kt + 1 < nk) cp_wait<1>(); else cp_wait<0>();
        __syncthreads();
        if (kt + 2 < nk) { load_stage((kt + 2) << 5, (kt + 2) % 3); cp_commit(); }
        __half* As = SH + (kt % 3) * GH_STAGE_H;
        __half* Bs = As + 6144;
#pragma unroll
        for (int kk = 0; kk < 2; kk++) {
            wmma::fragment<wmma::matrix_a, 16, 16, 16, __half, wmma::row_major> af[2];
            wmma::fragment<wmma::matrix_b, 16, 16, 16, __half, wmma::row_major> bf[4];
#pragma unroll
            for (int i = 0; i < 2; i++)
                wmma::load_matrix_sync(af[i], As + (wm * 32 + i * 16) * 48 + kk * 16, 48);
#pragma unroll
            for (int j = 0; j < 4; j++)
                wmma::load_matrix_sync(bf[j], Bs + (kk * 16) * 136 + wn * 64 + j * 16, 136);
#pragma unroll
            for (int i = 0; i < 2; i++)
#pragma unroll
                for (int j = 0; j < 4; j++)
                    wmma::mma_sync(acc[i][j], af[i], bf[j], acc[i][j]);
        }
    }
    __syncthreads();

    float* stg = (float*)sm;
#pragma unroll
    for (int i = 0; i < 2; i++)
#pragma unroll
        for (int j = 0; j < 4; j++)
            wmma::store_matrix_sync(stg + (wm * 32 + i * 16) * 132 + wn * 64 + j * 16,
                                    acc[i][j], 132, wmma::mem_row_major);
    __syncthreads();

#pragma unroll
    for (int e = 0; e < 16; e++) {
        int idx = tid + e * 256;
        int r = idx >> 5, c4 = idx & 31;
        float4 v = *(float4*)(stg + r * 132 + c4 * 4);
        float4 bb = *(const float4*)(bias + col0 + c4 * 4);
        v.x += bb.x; v.y += bb.y; v.z += bb.z; v.w += bb.w;
        if (RELU) { v.x = fmaxf(v.x, 0.f); v.y = fmaxf(v.y, 0.f); v.z = fmaxf(v.z, 0.f); v.w = fmaxf(v.w, 0.f); }
        size_t g = (size_t)(row0 + r) * N + col0 + c4 * 4;
        if (RESID) {
            float4 rr = *(const float4*)(resid + g);
            v.x += rr.x; v.y += rr.y; v.z += rr.z; v.w += rr.w;
        }
        if (WF32) *(float4*)(Cf + g) = v;
        if (WF16) {
            ((__half2*)(Ch + g))[0] = __floats2half2_rn(v.x, v.y);
            ((__half2*)(Ch + g))[1] = __floats2half2_rn(v.z, v.w);
        }
    }
}

// ---------------------------------------------------------------------------
// Split-fp16 GEMM (fp32-accurate) with FUSED ROPE epilogue.
// Computes C = (Ah+Al)(Bh+Bl) + bias in fp32, applies the reference's
// raw-angle "rotation" (same expressions as the old rope kernel, on the same
// fp32 values -> bit-identical), scales by `extra`, writes hi/lo fp16 split.
// ---------------------------------------------------------------------------
#define GS_STAGE_H 20992
#define GS_SMEM 83968

__global__ void __launch_bounds__(256) gemm_split_rope(
    const __half* __restrict__ Ah_, const __half* __restrict__ Al_,
    const __half* __restrict__ Bh_, const __half* __restrict__ Bl_,
    const float* __restrict__ bias,
    __half* __restrict__ Oh, __half* __restrict__ Ol,
    float extra, int M, int N, int K)
{
    extern __shared__ __align__(16) unsigned char sm[];
    __half* SH = (__half*)sm;
    __shared__ float sInv[32];

    const int tid = threadIdx.x;
    if (tid < 32)
        sInv[tid] = (float)exp(-0.28782313662425575 * (double)tid); // ln(1e4)/32

    const int warp = tid >> 5;
    const int wm = warp >> 1;
    const int wn = warp & 1;
    const int row0 = blockIdx.y * 128;
    const int col0 = blockIdx.x * 128;

    wmma::fragment<wmma::accumulator, 16, 16, 16, float> acc[2][4];
#pragma unroll
    for (int i = 0; i < 2; i++)
#pragma unroll
        for (int j = 0; j < 4; j++) wmma::fill_fragment(acc[i][j], 0.f);

    auto load_stage = [&](int k0, int s) {
        __half* Ahs = SH + s * GS_STAGE_H;
        __half* Als = Ahs + 6144;
        __half* Bhs = Als + 6144;
        __half* Bls = Bhs + 4352;
#pragma unroll
        for (int i = 0; i < 2; i++) {
            int c = tid + i * 256;
            int r = c >> 2, q = c & 3;
            size_t g = (size_t)(row0 + r) * K + k0 + q * 8;
            cp16(Ahs + r * 48 + q * 8, Ah_ + g);
            cp16(Als + r * 48 + q * 8, Al_ + g);
        }
#pragma unroll
        for (int i = 0; i < 2; i++) {
            int c = tid + i * 256;
            int r = c >> 4, q = c & 15;
            size_t g = (size_t)(k0 + r) * N + col0 + q * 8;
            cp16(Bhs + r * 136 + q * 8, Bh_ + g);
            cp16(Bls + r * 136 + q * 8, Bl_ + g);
        }
    };

    const int nk = K >> 5;
    load_stage(0, 0); cp_commit();
    for (int kt = 0; kt < nk; kt++) {
        cp_wait<0>();
        __syncthreads();
        if (kt + 1 < nk) { load_stage((kt + 1) << 5, (kt + 1) & 1); cp_commit(); }
        __half* Ahs = SH + (kt & 1) * GS_STAGE_H;
        __half* Als = Ahs + 6144;
        __half* Bhs = Als + 6144;
        __half* Bls = Bhs + 4352;
#pragma unroll
        for (int kk = 0; kk < 2; kk++) {
            wmma::fragment<wmma::matrix_a, 16, 16, 16, __half, wmma::row_major> afh[2], afl[2];
            wmma::fragment<wmma::matrix_b, 16, 16, 16, __half, wmma::row_major> bfh[4], bfl[4];
#pragma unroll
            for (int i = 0; i < 2; i++) {
                wmma::load_matrix_sync(afh[i], Ahs + (wm * 32 + i * 16) * 48 + kk * 16, 48);
                wmma::load_matrix_sync(afl[i], Als + (wm * 32 + i * 16) * 48 + kk * 16, 48);
            }
#pragma unroll
            for (int j = 0; j < 4; j++) {
                wmma::load_matrix_sync(bfh[j], Bhs + (kk * 16) * 136 + wn * 64 + j * 16, 136);
                wmma::load_matrix_sync(bfl[j], Bls + (kk * 16) * 136 + wn * 64 + j * 16, 136);
            }
#pragma unroll
            for (int i = 0; i < 2; i++)
#pragma unroll
                for (int j = 0; j < 4; j++) {
                    wmma::mma_sync(acc[i][j], afh[i], bfh[j], acc[i][j]);
                    wmma::mma_sync(acc[i][j], afh[i], bfl[j], acc[i][j]);
                    wmma::mma_sync(acc[i][j], afl[i], bfh[j], acc[i][j]);
                }
        }
    }
    __syncthreads();

    float* stg = (float*)sm;
#pragma unroll
    for (int i = 0; i < 2; i++)
#pragma unroll
        for (int j = 0; j < 4; j++)
            wmma::store_matrix_sync(stg + (wm * 32 + i * 16) * 132 + wn * 64 + j * 16,
                                    acc[i][j], 132, wmma::mem_row_major);
    __syncthreads();

#pragma unroll
    for (int e = 0; e < 16; e++) {
        int idx = tid + e * 256;
        int r = idx >> 5, c4 = idx & 31;
        float4 v = *(float4*)(stg + r * 132 + c4 * 4);
        float4 bb = *(const float4*)(bias + col0 + c4 * 4);
        float t0 = v.x + bb.x, t1 = v.y + bb.y, t2 = v.z + bb.z, t3 = v.w + bb.w;

        int gc = col0 + c4 * 4;          // global col, multiple of 4
        int dd = gc & 63;
        int j0 = dd >> 1;                // even
        int row = row0 + r;
        float fs = (float)(row & (SEQ - 1));

        int ic0 = (2 * j0 < 32) ? 2 * j0 : 2 * j0 - 32;
        int is0 = (2 * j0 + 1 < 32) ? 2 * j0 + 1 : 2 * j0 - 31;
        float ca0 = fs * sInv[ic0], sa0 = fs * sInv[is0];
        float o0 = (t0 * ca0 - t1 * sa0) * extra;
        float o1 = (t0 * sa0 + t1 * ca0) * extra;

        int j1 = j0 + 1;
        int ic1 = (2 * j1 < 32) ? 2 * j1 : 2 * j1 - 32;
        int is1 = (2 * j1 + 1 < 32) ? 2 * j1 + 1 : 2 * j1 - 31;
        float ca1 = fs * sInv[ic1], sa1 = fs * sInv[is1];
        float o2 = (t2 * ca1 - t3 * sa1) * extra;
        float o3 = (t2 * sa1 + t3 * ca1) * extra;

        size_t hb = (size_t)row * N + (gc & ~63);   // head base
        __half h0 = __float2half(o0), h2v = __float2half(o2);
        __half h1 = __float2half(o1), h3v = __float2half(o3);
        *(__half2*)(Oh + hb + j0)      = __halves2half2(h0, h2v);
        *(__half2*)(Oh + hb + 32 + j0) = __halves2half2(h1, h3v);
        *(__half2*)(Ol + hb + j0)      = __floats2half2_rn(o0 - __half2float(h0),
                                                           o2 - __half2float(h2v));
        *(__half2*)(Ol + hb + 32 + j0) = __floats2half2_rn(o1 - __half2float(h1),
                                                           o3 - __half2float(h3v));
    }
}

// ---------------------------------------------------------------------------
// FA2-style flash attention: grid (S/64, H, B), 128 threads (4 warps,
// 16 q-rows each). S/P/O live in registers (mma.m16n8k16 fragments);
// row stats via shfl within lane quads. K/V tiles in smem (cp.async,
// double-buffered, single barrier per tile). Split-fp16 QK^T (3 MMAs),
// accumulation order identical to the proven wmma version.
// ---------------------------------------------------------------------------
#define ATT_SMEM 55296

__global__ void __launch_bounds__(128) attn_kernel(
    const __half* __restrict__ qh, const __half* __restrict__ ql,
    const __half* __restrict__ kh, const __half* __restrict__ kl,
    const __half* __restrict__ v, __half* __restrict__ ctx)
{
    extern __shared__ __align__(16) unsigned char sm[];
    __half* KH = (__half*)sm;                 // [2][64][72]
    __half* KL = KH + 9216;
    __half* VT = KL + 9216;

    const int tid = threadIdx.x;
    const int w = tid >> 5;
    const int lane = tid & 31;
    const int gid = lane >> 2;        // 0..7
    const int qc  = (lane & 3) * 2;   // 0,2,4,6
    const int qt = blockIdx.x;
    const int h = blockIdx.y;
    const int b = blockIdx.z;
    const int hc = h * DHEAD;
    const int brow = b * SEQ;
    const int qrow0 = brow + qt * 64 + w * 16;

    // Q fragments (hi/lo), 4 dh-chunks of 16, direct from global
    uint32_t qAh[4][4], qAl[4][4];
#pragma unroll
    for (int kc = 0; kc < 4; kc++) {
        const __half* bh = qh + (size_t)qrow0 * DMODEL + hc + kc * 16;
        const __half* bl = ql + (size_t)qrow0 * DMODEL + hc + kc * 16;
        qAh[kc][0] = *(const uint32_t*)(bh + (size_t)gid * DMODEL + qc);
        qAh[kc][1] = *(const uint32_t*)(bh + (size_t)(gid + 8) * DMODEL + qc);
        qAh[kc][2] = *(const uint32_t*)(bh + (size_t)gid * DMODEL + qc + 8);
        qAh[kc][3] = *(const uint32_t*)(bh + (size_t)(gid + 8) * DMODEL + qc + 8);
        qAl[kc][0] = *(const uint32_t*)(bl + (size_t)gid * DMODEL + qc);
        qAl[kc][1] = *(const uint32_t*)(bl + (size_t)(gid + 8) * DMODEL + qc);
        qAl[kc][2] = *(const uint32_t*)(bl + (size_t)gid * DMODEL + qc + 8);
        qAl[kc][3] = *(const uint32_t*)(bl + (size_t)(gid + 8) * DMODEL + qc + 8);
    }

    float O[8][4];
#pragma unroll
    for (int t = 0; t < 8; t++)
        O[t][0] = O[t][1] = O[t][2] = O[t][3] = 0.f;
    float m0 = -1e30f, m1 = -1e30f, l0 = 0.f, l1 = 0.f;

    auto load_stage = [&](int kv, int s) {
#pragma unroll
        for (int i = 0; i < 4; i++) {
            int c = tid + i * 128;
            int rr = c >> 3, qq = c & 7;
            size_t g = (size_t)(brow + kv * 64 + rr) * DMODEL + hc + qq * 8;
            int so = s * 4608 + rr * 72 + qq * 8;
            cp16(KH + so, kh + g);
            cp16(KL + so, kl + g);
            cp16(VT + so, v + g);
        }
    };

    const int NT = SEQ / 64;
    load_stage(0, 0); cp_commit();

    for (int kt = 0; kt < NT; kt++) {
        cp_wait<0>();
        __syncthreads();
        if (kt + 1 < NT) { load_stage(kt + 1, (kt + 1) & 1); cp_commit(); }

        const int s = kt & 1;
        const __half* KHs = KH + s * 4608;
        const __half* KLs = KL + s * 4608;
        const __half* VTs = VT + s * 4608;

        // ---- S = Q @ K^T (split: qh*kh + qh*kl + ql*kh), 8 key n8-tiles ----
        float S[8][4];
#pragma unroll
        for (int t = 0; t < 8; t++) {
            S[t][0] = S[t][1] = S[t][2] = S[t][3] = 0.f;
#pragma unroll
            for (int kc = 0; kc < 4; kc++) {
                int koff = (t * 8 + gid) * 72 + kc * 16 + qc;
                uint32_t bh0 = *(const uint32_t*)(KHs + koff);
                uint32_t bh1 = *(const uint32_t*)(KHs + koff + 8);
                uint32_t bl0 = *(const uint32_t*)(KLs + koff);
                uint32_t bl1 = *(const uint32_t*)(KLs + koff + 8);
                mma16816(S[t], qAh[kc], bh0, bh1);
                mma16816(S[t], qAh[kc], bl0, bl1);
                mma16816(S[t], qAl[kc], bh0, bh1);
            }
        }

        // ---- online softmax on registers ----
        float mt0 = -1e30f, mt1 = -1e30f;
#pragma unroll
        for (int t = 0; t < 8; t++) {
            mt0 = fmaxf(mt0, fmaxf(S[t][0], S[t][1]));
            mt1 = fmaxf(mt1, fmaxf(S[t][2], S[t][3]));
        }
        mt0 = fmaxf(mt0, __shfl_xor_sync(0xffffffffu, mt0, 1));
        mt0 = fmaxf(mt0, __shfl_xor_sync(0xffffffffu, mt0, 2));
        mt1 = fmaxf(mt1, __shfl_xor_sync(0xffffffffu, mt1, 1));
        mt1 = fmaxf(mt1, __shfl_xor_sync(0xffffffffu, mt1, 2));
        float mn0 = fmaxf(m0, mt0), mn1 = fmaxf(m1, mt1);
        float al0 = __expf(m0 - mn0), al1 = __expf(m1 - mn1);

        uint32_t pA[4][4];
        float ls0 = 0.f, ls1 = 0.f;
#pragma unroll
        for (int t = 0; t < 8; t++) {
            float p0 = __expf(S[t][0] - mn0);
            float p1 = __expf(S[t][1] - mn0);
            float p2 = __expf(S[t][2] - mn1);
            float p3 = __expf(S[t][3] - mn1);
            ls0 += p0 + p1;
            ls1 += p2 + p3;
            pA[t >> 1][(t & 1) * 2 + 0] = f2u2(p0, p1);
            pA[t >> 1][(t & 1) * 2 + 1] = f2u2(p2, p3);
        }
        ls0 += __shfl_xor_sync(0xffffffffu, ls0, 1);
        ls0 += __shfl_xor_sync(0xffffffffu, ls0, 2);
        ls1 += __shfl_xor_sync(0xffffffffu, ls1, 1);
        ls1 += __shfl_xor_sync(0xffffffffu, ls1, 2);
        l0 = l0 * al0 + ls0;
        l1 = l1 * al1 + ls1;
        m0 = mn0; m1 = mn1;
#pragma unroll
        for (int t = 0; t < 8; t++) {
            O[t][0] *= al0; O[t][1] *= al0;
            O[t][2] *= al1; O[t][3] *= al1;
        }

        // ---- O += P @ V (8 dh n8-tiles x 4 key chunks) ----
#pragma unroll
        for (int t = 0; t < 8; t++) {
#pragma unroll
            for (int kc = 0; kc < 4; kc++) {
                int vr = (kc * 16 + qc) * 72 + t * 8 + gid;
                __half x0 = VTs[vr];
                __half x1 = VTs[vr + 72];
                __half x2 = VTs[vr + 8 * 72];
                __half x3 = VTs[vr + 9 * 72];
                mma16816(O[t], pA[kc], h2u(x0, x1), h2u(x2, x3));
            }
        }
    }

    // ---- epilogue: O / l ----
    float inv0 = 1.f / l0, inv1 = 1.f / l1;
#pragma unroll
    for (int t = 0; t < 8; t++) {
        *(__half2*)(ctx + (size_t)(qrow0 + gid) * DMODEL + hc + t * 8 + qc) =
            __floats2half2_rn(O[t][0] * inv0, O[t][1] * inv0);
        *(__half2*)(ctx + (size_t)(qrow0 + gid + 8) * DMODEL + hc + t * 8 + qc) =
            __floats2half2_rn(O[t][2] * inv1, O[t][3] * inv1);
    }
}

// ---------------------------------------------------------------------------
// LayerNorm over 1024 cols, block=256, one row per block. Optional fp16 copy.
// ---------------------------------------------------------------------------
__global__ void __launch_bounds__(256) ln_kernel(
    const float* __restrict__ in, const float* __restrict__ g,
    const float* __restrict__ be, float* __restrict__ outf,
    __half* __restrict__ outh)
{
    int row = blockIdx.x;
    int tid = threadIdx.x;
    float4 v = ((const float4*)(in + (size_t)row * DMODEL))[tid];
    float s  = v.x + v.y + v.z + v.w;
    float ss = v.x * v.x + v.y * v.y + v.z * v.z + v.w * v.w;
#pragma unroll
    for (int o = 16; o > 0; o >>= 1) {
        s  += __shfl_down_sync(0xffffffffu, s, o);
        ss += __shfl_down_sync(0xffffffffu, ss, o);
    }
    __shared__ float shs[8], shss[8], smu, srs;
    int lane = tid & 31, wid = tid >> 5;
    if (lane == 0) { shs[wid] = s; shss[wid] = ss; }
    __syncthreads();
    if (tid == 0) {
        float S = 0.f, SS = 0.f;
#pragma unroll
        for (int i = 0; i < 8; i++) { S += shs[i]; SS += shss[i]; }
        float mu = S * (1.f / 1024.f);
        float var = SS * (1.f / 1024.f) - mu * mu;
        smu = mu;
        srs = rsqrtf(var + 1e-5f);
    }
    __syncthreads();
    float mu = smu, rs = srs;
    float4 gv = ((const float4*)g)[tid];
    float4 bv = ((const float4*)be)[tid];
    float4 o;
    o.x = (v.x - mu) * rs * gv.x + bv.x;
    o.y = (v.y - mu) * rs * gv.y + bv.y;
    o.z = (v.z - mu) * rs * gv.z + bv.z;
    o.w = (v.w - mu) * rs * gv.w + bv.w;
    ((float4*)(outf + (size_t)row * DMODEL))[tid] = o;
    if (outh) {
        ((__half2*)(outh + (size_t)row * DMODEL))[2 * tid]     = __floats2half2_rn(o.x, o.y);
        ((__half2*)(outh + (size_t)row * DMODEL))[2 * tid + 1] = __floats2half2_rn(o.z, o.w);
    }
}

extern "C" void kernel_launch(void* const* d_in, const int* in_sizes, int n_in,
                              void* d_out, int out_size) {
    const float* x   = (const float*)d_in[0];
    const float* wq  = (const float*)d_in[1];
    const float* bq  = (const float*)d_in[2];
    const float* wk  = (const float*)d_in[3];
    const float* bk  = (const float*)d_in[4];
    const float* wv  = (const float*)d_in[5];
    const float* bv  = (const float*)d_in[6];
    const float* wo  = (const float*)d_in[7];
    const float* bo  = (const float*)d_in[8];
    const float* w1  = (const float*)d_in[9];
    const float* b1  = (const float*)d_in[10];
    const float* w2  = (const float*)d_in[11];
    const float* b2  = (const float*)d_in[12];
    const float* g1  = (const float*)d_in[13];
    const float* be1 = (const float*)d_in[14];
    const float* g2  = (const float*)d_in[15];
    const float* be2 = (const float*)d_in[16];
    float* out = (float*)d_out;

    void *p;
    cudaGetSymbolAddress(&p, g_xh);   __half* xh  = (__half*)p;
    cudaGetSymbolAddress(&p, g_xl);   __half* xl  = (__half*)p;
    cudaGetSymbolAddress(&p, g_wqh);  __half* wqh = (__half*)p;
    cudaGetSymbolAddress(&p, g_wql);  __half* wql = (__half*)p;
    cudaGetSymbolAddress(&p, g_wkh);  __half* wkh = (__half*)p;
    cudaGetSymbolAddress(&p, g_wkl);  __half* wkl = (__half*)p;
    cudaGetSymbolAddress(&p, g_wvh);  __half* wvh = (__half*)p;
    cudaGetSymbolAddress(&p, g_woh);  __half* woh = (__half*)p;
    cudaGetSymbolAddress(&p, g_w1h);  __half* w1h = (__half*)p;
    cudaGetSymbolAddress(&p, g_w2h);  __half* w2h = (__half*)p;
    cudaGetSymbolAddress(&p, g_qrh);  __half* qrh = (__half*)p;
    cudaGetSymbolAddress(&p, g_qrl);  __half* qrl = (__half*)p;
    cudaGetSymbolAddress(&p, g_krh);  __half* krh = (__half*)p;
    cudaGetSymbolAddress(&p, g_krl);  __half* krl = (__half*)p;
    cudaGetSymbolAddress(&p, g_vh);   __half* vh  = (__half*)p;
    cudaGetSymbolAddress(&p, g_ctx);  __half* ctx = (__half*)p;
    cudaGetSymbolAddress(&p, g_res1); float*  res1 = (float*)p;
    cudaGetSymbolAddress(&p, g_hbuf); float*  hbuf = (float*)p;
    cudaGetSymbolAddress(&p, g_hh);   __half* hh  = (__half*)p;
    cudaGetSymbolAddress(&p, g_ff1);  __half* ff1 = (__half*)p;
    cudaGetSymbolAddress(&p, g_res2); float*  res2 = (float*)p;

    cudaFuncSetAttribute(gemm_h<false, false, false, true>,
                         cudaFuncAttributeMaxDynamicSharedMemorySize, GH_SMEM);
    cudaFuncSetAttribute(gemm_h<false, true, true, false>,
                         cudaFuncAttributeMaxDynamicSharedMemorySize, GH_SMEM);
    cudaFuncSetAttribute(gemm_h<true, false, false, true>,
                         cudaFuncAttributeMaxDynamicSharedMemorySize, GH_SMEM);
    cudaFuncSetAttribute(gemm_split_rope,
                         cudaFuncAttributeMaxDynamicSharedMemorySize, GS_SMEM);
    cudaFuncSetAttribute(attn_kernel,
                         cudaFuncAttributeMaxDynamicSharedMemorySize, ATT_SMEM);

    // launch 0: all conversions fused
    conv_all<<<CV_B6 / 256, 256>>>(x, wq, wk, wv, wo, w1, w2,
                                   xh, xl, wqh, wql, wkh, wkl, wvh, woh, w1h, w2h);

    dim3 grid1(DMODEL / 128, ROWS / 128);   // (8, 64)
    dim3 gridF(DFF / 128,    ROWS / 128);   // (32, 64)

    // launch 1: V projection (plain fp16)
    gemm_h<false, false, false, true><<<grid1, 256, GH_SMEM>>>(xh, wvh, bv, nullptr, nullptr, vh, ROWS, DMODEL, DMODEL);

    // launches 2-3: Q,K split projections with fused rope (hi/lo fp16 out)
    gemm_split_rope<<<grid1, 256, GS_SMEM>>>(xh, xl, wqh, wql, bq, qrh, qrl, 0.125f, ROWS, DMODEL, DMODEL);
    gemm_split_rope<<<grid1, 256, GS_SMEM>>>(xh, xl, wkh, wkl, bk, krh, krl, 1.0f,   ROWS, DMODEL, DMODEL);

    // launch 4: attention (register-resident FA2)
    attn_kernel<<<dim3(SEQ / 64, NHEADS, BATCH), 128, ATT_SMEM>>>(qrh, qrl, krh, krl, vh, ctx);

    // launch 5: output projection + residual(x)
    gemm_h<false, true, true, false><<<grid1, 256, GH_SMEM>>>(ctx, woh, bo, x, res1, nullptr, ROWS, DMODEL, DMODEL);

    // LN1 -> h (fp32 + fp16)
    ln_kernel<<<ROWS, 256>>>(res1, g1, be1, hbuf, hh);

    // FFN
    gemm_h<true,  false, false, true ><<<gridF, 256, GH_SMEM>>>(hh, w1h, b1, nullptr, nullptr, ff1, ROWS, DFF, DMODEL);
    gemm_h<false, true,  true,  false><<<grid1, 256, GH_SMEM>>>(ff1, w2h, b2, hbuf, res2, nullptr, ROWS, DMODEL, DFF);

    // LN2 -> output
    ln_kernel<<<ROWS, 256>>>(res2, g2, be2, out, nullptr);
}

// round 12
// speedup vs baseline: 1.5358x; 1.0733x over previous
#include <cuda_runtime.h>
#include <cuda_fp16.h>
#include <mma.h>
#include <cstdint>

using namespace nvcuda;

// ---------------------------------------------------------------------------
#define BATCH 4
#define SEQ 2048
#define ROWS (BATCH * SEQ)       // 8192
#define DMODEL 1024
#define NHEADS 16
#define DHEAD 64
#define DFF 4096

// ---------------------------------------------------------------------------
// Scratch (static device globals; no allocation allowed)
// ---------------------------------------------------------------------------
__device__ __half g_xh[ROWS * DMODEL];
__device__ __half g_xl[ROWS * DMODEL];
__device__ __half g_wqh[DMODEL * DMODEL];
__device__ __half g_wql[DMODEL * DMODEL];
__device__ __half g_wkh[DMODEL * DMODEL];
__device__ __half g_wkl[DMODEL * DMODEL];
__device__ __half g_wvh[DMODEL * DMODEL];
__device__ __half g_woh[DMODEL * DMODEL];
__device__ __half g_w1h[DMODEL * DFF];
__device__ __half g_w2h[DFF * DMODEL];

__device__ __half g_qrh[ROWS * DMODEL];
__device__ __half g_qrl[ROWS * DMODEL];
__device__ __half g_krh[ROWS * DMODEL];
__device__ __half g_krl[ROWS * DMODEL];
__device__ __half g_vh[ROWS * DMODEL];
__device__ __half g_ctx[ROWS * DMODEL];
__device__ float  g_res1[ROWS * DMODEL];
__device__ float  g_hbuf[ROWS * DMODEL];
__device__ __half g_hh[ROWS * DMODEL];
__device__ __half g_ff1[ROWS * DFF];
__device__ float  g_res2[ROWS * DMODEL];

// ---------------------------------------------------------------------------
// cp.async + mma helpers
// ---------------------------------------------------------------------------
__device__ __forceinline__ void cp16(void* s, const void* g) {
    unsigned int sa = (unsigned int)__cvta_generic_to_shared(s);
    asm volatile("cp.async.cg.shared.global [%0], [%1], 16;\n" :: "r"(sa), "l"(g) : "memory");
}
__device__ __forceinline__ void cp_commit() {
    asm volatile("cp.async.commit_group;\n" ::: "memory");
}
template<int N> __device__ __forceinline__ void cp_wait() {
    asm volatile("cp.async.wait_group %0;\n" :: "n"(N) : "memory");
}

__device__ __forceinline__ void mma16816(float* c, const uint32_t* a,
                                         uint32_t b0, uint32_t b1) {
    asm volatile(
        "mma.sync.aligned.m16n8k16.row.col.f32.f16.f16.f32 "
        "{%0,%1,%2,%3}, {%4,%5,%6,%7}, {%8,%9}, {%0,%1,%2,%3};\n"
        : "+f"(c[0]), "+f"(c[1]), "+f"(c[2]), "+f"(c[3])
        : "r"(a[0]), "r"(a[1]), "r"(a[2]), "r"(a[3]), "r"(b0), "r"(b1));
}

__device__ __forceinline__ uint32_t h2u(__half a, __half b) {
    __half2 t = __halves2half2(a, b);
    return *(uint32_t*)&t;
}
__device__ __forceinline__ uint32_t f2u2(float a, float b) {
    __half2 t = __floats2half2_rn(a, b);
    return *(uint32_t*)&t;
}

// ---------------------------------------------------------------------------
// Fused conversion kernel
// ---------------------------------------------------------------------------
#define X4  (ROWS * DMODEL / 4)
#define W4  (DMODEL * DMODEL / 4)
#define F4  (DMODEL * DFF / 4)
#define CV_B0 X4
#define CV_B1 (CV_B0 + W4)
#define CV_B2 (CV_B1 + W4)
#define CV_B3 (CV_B2 + W4)
#define CV_B4 (CV_B3 + W4)
#define CV_B5 (CV_B4 + F4)
#define CV_B6 (CV_B5 + F4)

__device__ __forceinline__ void cv_split(const float* __restrict__ in,
                                         __half* __restrict__ hi,
                                         __half* __restrict__ lo, int i) {
    float4 v = ((const float4*)in)[i];
    __half hx = __float2half(v.x), hy = __float2half(v.y);
    __half hz = __float2half(v.z), hw = __float2half(v.w);
    ((__half2*)hi)[2 * i]     = __halves2half2(hx, hy);
    ((__half2*)hi)[2 * i + 1] = __halves2half2(hz, hw);
    ((__half2*)lo)[2 * i]     = __floats2half2_rn(v.x - __half2float(hx),
                                                  v.y - __half2float(hy));
    ((__half2*)lo)[2 * i + 1] = __floats2half2_rn(v.z - __half2float(hz),
                                                  v.w - __half2float(hw));
}
__device__ __forceinline__ void cv_plain(const float* __restrict__ in,
                                         __half* __restrict__ out, int i) {
    float4 v = ((const float4*)in)[i];
    ((__half2*)out)[2 * i]     = __floats2half2_rn(v.x, v.y);
    ((__half2*)out)[2 * i + 1] = __floats2half2_rn(v.z, v.w);
}

__global__ void __launch_bounds__(256) conv_all(
    const float* __restrict__ x,  const float* __restrict__ wq,
    const float* __restrict__ wk, const float* __restrict__ wv,
    const float* __restrict__ wo, const float* __restrict__ w1,
    const float* __restrict__ w2,
    __half* __restrict__ xh,  __half* __restrict__ xl,
    __half* __restrict__ wqh, __half* __restrict__ wql,
    __half* __restrict__ wkh, __half* __restrict__ wkl,
    __half* __restrict__ wvh, __half* __restrict__ woh,
    __half* __restrict__ w1h, __half* __restrict__ w2h)
{
    int i = blockIdx.x * 256 + threadIdx.x;
    if (i < CV_B0)      cv_split(x,  xh,  xl,  i);
    else if (i < CV_B1) cv_split(wq, wqh, wql, i - CV_B0);
    else if (i < CV_B2) cv_split(wk, wkh, wkl, i - CV_B1);
    else if (i < CV_B3) cv_plain(wv, wvh, i - CV_B2);
    else if (i < CV_B4) cv_plain(wo, woh, i - CV_B3);
    else if (i < CV_B5) cv_plain(w1, w1h, i - CV_B4);
    else if (i < CV_B6) cv_plain(w2, w2h, i - CV_B5);
}

// ---------------------------------------------------------------------------
// Plain fp16 GEMM: 128x128x32 tiles, cp.async 3-stage pipeline.
// ---------------------------------------------------------------------------
#define GH_STAGE_H 10496
#define GH_SMEM 67584

template<bool RELU, bool RESID, bool WF32, bool WF16>
__global__ void __launch_bounds__(256) gemm_h(
    const __half* __restrict__ A, const __half* __restrict__ Bw,
    const float* __restrict__ bias, const float* __restrict__ resid,
    float* __restrict__ Cf, __half* __restrict__ Ch,
    int M, int N, int K)
{
    extern __shared__ __align__(16) unsigned char sm[];
    __half* SH = (__half*)sm;

    const int tid = threadIdx.x;
    const int warp = tid >> 5;
    const int wm = warp >> 1;
    const int wn = warp & 1;
    const int row0 = blockIdx.y * 128;
    const int col0 = blockIdx.x * 128;

    wmma::fragment<wmma::accumulator, 16, 16, 16, float> acc[2][4];
#pragma unroll
    for (int i = 0; i < 2; i++)
#pragma unroll
        for (int j = 0; j < 4; j++) wmma::fill_fragment(acc[i][j], 0.f);

    auto load_stage = [&](int k0, int s) {
        __half* As = SH + s * GH_STAGE_H;
        __half* Bs = As + 6144;
#pragma unroll
        for (int i = 0; i < 2; i++) {
            int c = tid + i * 256;
            int r = c >> 2, q = c & 3;
            cp16(As + r * 48 + q * 8, A + (size_t)(row0 + r) * K + k0 + q * 8);
        }
#pragma unroll
        for (int i = 0; i < 2; i++) {
            int c = tid + i * 256;
            int r = c >> 4, q = c & 15;
            cp16(Bs + r * 136 + q * 8, Bw + (size_t)(k0 + r) * N + col0 + q * 8);
        }
    };

    const int nk = K >> 5;
    load_stage(0, 0); cp_commit();
    load_stage(32, 1); cp_commit();
    for (int kt = 0; kt < nk; kt++) {
        if (kt + 1 < nk) cp_wait<1>(); else cp_wait<0>();
        __syncthreads();
        if (kt + 2 < nk) { load_stage((kt + 2) << 5, (kt + 2) % 3); cp_commit(); }
        __half* As = SH + (kt % 3) * GH_STAGE_H;
        __half* Bs = As + 6144;
#pragma unroll
        for (int kk = 0; kk < 2; kk++) {
            wmma::fragment<wmma::matrix_a, 16, 16, 16, __half, wmma::row_major> af[2];
            wmma::fragment<wmma::matrix_b, 16, 16, 16, __half, wmma::row_major> bf[4];
#pragma unroll
            for (int i = 0; i < 2; i++)
                wmma::load_matrix_sync(af[i], As + (wm * 32 + i * 16) * 48 + kk * 16, 48);
#pragma unroll
            for (int j = 0; j < 4; j++)
                wmma::load_matrix_sync(bf[j], Bs + (kk * 16) * 136 + wn * 64 + j * 16, 136);
#pragma unroll
            for (int i = 0; i < 2; i++)
#pragma unroll
                for (int j = 0; j < 4; j++)
                    wmma::mma_sync(acc[i][j], af[i], bf[j], acc[i][j]);
        }
    }
    __syncthreads();

    float* stg = (float*)sm;
#pragma unroll
    for (int i = 0; i < 2; i++)
#pragma unroll
        for (int j = 0; j < 4; j++)
            wmma::store_matrix_sync(stg + (wm * 32 + i * 16) * 132 + wn * 64 + j * 16,
                                    acc[i][j], 132, wmma::mem_row_major);
    __syncthreads();

#pragma unroll
    for (int e = 0; e < 16; e++) {
        int idx = tid + e * 256;
        int r = idx >> 5, c4 = idx & 31;
        float4 v = *(float4*)(stg + r * 132 + c4 * 4);
        float4 bb = *(const float4*)(bias + col0 + c4 * 4);
        v.x += bb.x; v.y += bb.y; v.z += bb.z; v.w += bb.w;
        if (RELU) { v.x = fmaxf(v.x, 0.f); v.y = fmaxf(v.y, 0.f); v.z = fmaxf(v.z, 0.f); v.w = fmaxf(v.w, 0.f); }
        size_t g = (size_t)(row0 + r) * N + col0 + c4 * 4;
        if (RESID) {
            float4 rr = *(const float4*)(resid + g);
            v.x += rr.x; v.y += rr.y; v.z += rr.z; v.w += rr.w;
        }
        if (WF32) *(float4*)(Cf + g) = v;
        if (WF16) {
            ((__half2*)(Ch + g))[0] = __floats2half2_rn(v.x, v.y);
            ((__half2*)(Ch + g))[1] = __floats2half2_rn(v.z, v.w);
        }
    }
}

// ---------------------------------------------------------------------------
// Split-fp16 GEMM (fp32-accurate) with FUSED ROPE epilogue.
// __launch_bounds__(256, 2): cap regs at 128 for 2 CTAs/SM. Inner loop
// processes B-fragments in pairs to shrink the live set. Per-acc-tile
// MMA order unchanged -> bit-identical results.
// ---------------------------------------------------------------------------
#define GS_STAGE_H 20992
#define GS_SMEM 83968

__global__ void __launch_bounds__(256, 2) gemm_split_rope(
    const __half* __restrict__ Ah_, const __half* __restrict__ Al_,
    const __half* __restrict__ Bh_, const __half* __restrict__ Bl_,
    const float* __restrict__ bias,
    __half* __restrict__ Oh, __half* __restrict__ Ol,
    float extra, int M, int N, int K)
{
    extern __shared__ __align__(16) unsigned char sm[];
    __half* SH = (__half*)sm;
    __shared__ float sInv[32];

    const int tid = threadIdx.x;
    if (tid < 32)
        sInv[tid] = (float)exp(-0.28782313662425575 * (double)tid); // ln(1e4)/32

    const int warp = tid >> 5;
    const int wm = warp >> 1;
    const int wn = warp & 1;
    const int row0 = blockIdx.y * 128;
    const int col0 = blockIdx.x * 128;

    wmma::fragment<wmma::accumulator, 16, 16, 16, float> acc[2][4];
#pragma unroll
    for (int i = 0; i < 2; i++)
#pragma unroll
        for (int j = 0; j < 4; j++) wmma::fill_fragment(acc[i][j], 0.f);

    auto load_stage = [&](int k0, int s) {
        __half* Ahs = SH + s * GS_STAGE_H;
        __half* Als = Ahs + 6144;
        __half* Bhs = Als + 6144;
        __half* Bls = Bhs + 4352;
#pragma unroll
        for (int i = 0; i < 2; i++) {
            int c = tid + i * 256;
            int r = c >> 2, q = c & 3;
            size_t g = (size_t)(row0 + r) * K + k0 + q * 8;
            cp16(Ahs + r * 48 + q * 8, Ah_ + g);
            cp16(Als + r * 48 + q * 8, Al_ + g);
        }
#pragma unroll
        for (int i = 0; i < 2; i++) {
            int c = tid + i * 256;
            int r = c >> 4, q = c & 15;
            size_t g = (size_t)(k0 + r) * N + col0 + q * 8;
            cp16(Bhs + r * 136 + q * 8, Bh_ + g);
            cp16(Bls + r * 136 + q * 8, Bl_ + g);
        }
    };

    const int nk = K >> 5;
    load_stage(0, 0); cp_commit();
    for (int kt = 0; kt < nk; kt++) {
        cp_wait<0>();
        __syncthreads();
        if (kt + 1 < nk) { load_stage((kt + 1) << 5, (kt + 1) & 1); cp_commit(); }
        __half* Ahs = SH + (kt & 1) * GS_STAGE_H;
        __half* Als = Ahs + 6144;
        __half* Bhs = Als + 6144;
        __half* Bls = Bhs + 4352;
#pragma unroll
        for (int kk = 0; kk < 2; kk++) {
            wmma::fragment<wmma::matrix_a, 16, 16, 16, __half, wmma::row_major> afh[2], afl[2];
#pragma unroll
            for (int i = 0; i < 2; i++) {
                wmma::load_matrix_sync(afh[i], Ahs + (wm * 32 + i * 16) * 48 + kk * 16, 48);
                wmma::load_matrix_sync(afl[i], Als + (wm * 32 + i * 16) * 48 + kk * 16, 48);
            }
#pragma unroll
            for (int jj = 0; jj < 2; jj++) {
                wmma::fragment<wmma::matrix_b, 16, 16, 16, __half, wmma::row_major> bfh2[2], bfl2[2];
#pragma unroll
                for (int j2 = 0; j2 < 2; j2++) {
                    int j = jj * 2 + j2;
                    wmma::load_matrix_sync(bfh2[j2], Bhs + (kk * 16) * 136 + wn * 64 + j * 16, 136);
                    wmma::load_matrix_sync(bfl2[j2], Bls + (kk * 16) * 136 + wn * 64 + j * 16, 136);
                }
#pragma unroll
                for (int i = 0; i < 2; i++)
#pragma unroll
                    for (int j2 = 0; j2 < 2; j2++) {
                        int j = jj * 2 + j2;
                        wmma::mma_sync(acc[i][j], afh[i], bfh2[j2], acc[i][j]);
                        wmma::mma_sync(acc[i][j], afh[i], bfl2[j2], acc[i][j]);
                        wmma::mma_sync(acc[i][j], afl[i], bfh2[j2], acc[i][j]);
                    }
            }
        }
    }
    __syncthreads();

    float* stg = (float*)sm;
#pragma unroll
    for (int i = 0; i < 2; i++)
#pragma unroll
        for (int j = 0; j < 4; j++)
            wmma::store_matrix_sync(stg + (wm * 32 + i * 16) * 132 + wn * 64 + j * 16,
                                    acc[i][j], 132, wmma::mem_row_major);
    __syncthreads();

#pragma unroll
    for (int e = 0; e < 16; e++) {
        int idx = tid + e * 256;
        int r = idx >> 5, c4 = idx & 31;
        float4 v = *(float4*)(stg + r * 132 + c4 * 4);
        float4 bb = *(const float4*)(bias + col0 + c4 * 4);
        float t0 = v.x + bb.x, t1 = v.y + bb.y, t2 = v.z + bb.z, t3 = v.w + bb.w;

        int gc = col0 + c4 * 4;
        int dd = gc & 63;
        int j0 = dd >> 1;
        int row = row0 + r;
        float fs = (float)(row & (SEQ - 1));

        int ic0 = (2 * j0 < 32) ? 2 * j0 : 2 * j0 - 32;
        int is0 = (2 * j0 + 1 < 32) ? 2 * j0 + 1 : 2 * j0 - 31;
        float ca0 = fs * sInv[ic0], sa0 = fs * sInv[is0];
        float o0 = (t0 * ca0 - t1 * sa0) * extra;
        float o1 = (t0 * sa0 + t1 * ca0) * extra;

        int j1 = j0 + 1;
        int ic1 = (2 * j1 < 32) ? 2 * j1 : 2 * j1 - 32;
        int is1 = (2 * j1 + 1 < 32) ? 2 * j1 + 1 : 2 * j1 - 31;
        float ca1 = fs * sInv[ic1], sa1 = fs * sInv[is1];
        float o2 = (t2 * ca1 - t3 * sa1) * extra;
        float o3 = (t2 * sa1 + t3 * ca1) * extra;

        size_t hb = (size_t)row * N + (gc & ~63);
        __half h0 = __float2half(o0), h2v = __float2half(o2);
        __half h1 = __float2half(o1), h3v = __float2half(o3);
        *(__half2*)(Oh + hb + j0)      = __halves2half2(h0, h2v);
        *(__half2*)(Oh + hb + 32 + j0) = __halves2half2(h1, h3v);
        *(__half2*)(Ol + hb + j0)      = __floats2half2_rn(o0 - __half2float(h0),
                                                           o2 - __half2float(h2v));
        *(__half2*)(Ol + hb + 32 + j0) = __floats2half2_rn(o1 - __half2float(h1),
                                                           o3 - __half2float(h3v));
    }
}

// ---------------------------------------------------------------------------
// FA2-style flash attention, __launch_bounds__(128, 3) for 12 warps/SM.
// ---------------------------------------------------------------------------
#define ATT_SMEM 55296

__global__ void __launch_bounds__(128, 3) attn_kernel(
    const __half* __restrict__ qh, const __half* __restrict__ ql,
    const __half* __restrict__ kh, const __half* __restrict__ kl,
    const __half* __restrict__ v, __half* __restrict__ ctx)
{
    extern __shared__ __align__(16) unsigned char sm[];
    __half* KH = (__half*)sm;                 // [2][64][72]
    __half* KL = KH + 9216;
    __half* VT = KL + 9216;

    const int tid = threadIdx.x;
    const int w = tid >> 5;
    const int lane = tid & 31;
    const int gid = lane >> 2;
    const int qc  = (lane & 3) * 2;
    const int qt = blockIdx.x;
    const int h = blockIdx.y;
    const int b = blockIdx.z;
    const int hc = h * DHEAD;
    const int brow = b * SEQ;
    const int qrow0 = brow + qt * 64 + w * 16;

    uint32_t qAh[4][4], qAl[4][4];
#pragma unroll
    for (int kc = 0; kc < 4; kc++) {
        const __half* bh = qh + (size_t)qrow0 * DMODEL + hc + kc * 16;
        const __half* bl = ql + (size_t)qrow0 * DMODEL + hc + kc * 16;
        qAh[kc][0] = *(const uint32_t*)(bh + (size_t)gid * DMODEL + qc);
        qAh[kc][1] = *(const uint32_t*)(bh + (size_t)(gid + 8) * DMODEL + qc);
        qAh[kc][2] = *(const uint32_t*)(bh + (size_t)gid * DMODEL + qc + 8);
        qAh[kc][3] = *(const uint32_t*)(bh + (size_t)(gid + 8) * DMODEL + qc + 8);
        qAl[kc][0] = *(const uint32_t*)(bl + (size_t)gid * DMODEL + qc);
        qAl[kc][1] = *(const uint32_t*)(bl + (size_t)(gid + 8) * DMODEL + qc);
        qAl[kc][2] = *(const uint32_t*)(bl + (size_t)gid * DMODEL + qc + 8);
        qAl[kc][3] = *(const uint32_t*)(bl + (size_t)(gid + 8) * DMODEL + qc + 8);
    }

    float O[8][4];
#pragma unroll
    for (int t = 0; t < 8; t++)
        O[t][0] = O[t][1] = O[t][2] = O[t][3] = 0.f;
    float m0 = -1e30f, m1 = -1e30f, l0 = 0.f, l1 = 0.f;

    auto load_stage = [&](int kv, int s) {
#pragma unroll
        for (int i = 0; i < 4; i++) {
            int c = tid + i * 128;
            int rr = c >> 3, qq = c & 7;
            size_t g = (size_t)(brow + kv * 64 + rr) * DMODEL + hc + qq * 8;
            int so = s * 4608 + rr * 72 + qq * 8;
            cp16(KH + so, kh + g);
            cp16(KL + so, kl + g);
            cp16(VT + so, v + g);
        }
    };

    const int NT = SEQ / 64;
    load_stage(0, 0); cp_commit();

    for (int kt = 0; kt < NT; kt++) {
        cp_wait<0>();
        __syncthreads();
        if (kt + 1 < NT) { load_stage(kt + 1, (kt + 1) & 1); cp_commit(); }

        const int s = kt & 1;
        const __half* KHs = KH + s * 4608;
        const __half* KLs = KL + s * 4608;
        const __half* VTs = VT + s * 4608;

        float S[8][4];
#pragma unroll
        for (int t = 0; t < 8; t++) {
            S[t][0] = S[t][1] = S[t][2] = S[t][3] = 0.f;
#pragma unroll
            for (int kc = 0; kc < 4; kc++) {
                int koff = (t * 8 + gid) * 72 + kc * 16 + qc;
                uint32_t bh0 = *(const uint32_t*)(KHs + koff);
                uint32_t bh1 = *(const uint32_t*)(KHs + koff + 8);
                uint32_t bl0 = *(const uint32_t*)(KLs + koff);
                uint32_t bl1 = *(const uint32_t*)(KLs + koff + 8);
                mma16816(S[t], qAh[kc], bh0, bh1);
                mma16816(S[t], qAh[kc], bl0, bl1);
                mma16816(S[t], qAl[kc], bh0, bh1);
            }
        }

        float mt0 = -1e30f, mt1 = -1e30f;
#pragma unroll
        for (int t = 0; t < 8; t++) {
            mt0 = fmaxf(mt0, fmaxf(S[t][0], S[t][1]));
            mt1 = fmaxf(mt1, fmaxf(S[t][2], S[t][3]));
        }
        mt0 = fmaxf(mt0, __shfl_xor_sync(0xffffffffu, mt0, 1));
        mt0 = fmaxf(mt0, __shfl_xor_sync(0xffffffffu, mt0, 2));
        mt1 = fmaxf(mt1, __shfl_xor_sync(0xffffffffu, mt1, 1));
        mt1 = fmaxf(mt1, __shfl_xor_sync(0xffffffffu, mt1, 2));
        float mn0 = fmaxf(m0, mt0), mn1 = fmaxf(m1, mt1);
        float al0 = __expf(m0 - mn0), al1 = __expf(m1 - mn1);

        uint32_t pA[4][4];
        float ls0 = 0.f, ls1 = 0.f;
#pragma unroll
        for (int t = 0; t < 8; t++) {
            float p0 = __expf(S[t][0] - mn0);
            float p1 = __expf(S[t][1] - mn0);
            float p2 = __expf(S[t][2] - mn1);
            float p3 = __expf(S[t][3] - mn1);
            ls0 += p0 + p1;
            ls1 += p2 + p3;
            pA[t >> 1][(t & 1) * 2 + 0] = f2u2(p0, p1);
            pA[t >> 1][(t & 1) * 2 + 1] = f2u2(p2, p3);
        }
        ls0 += __shfl_xor_sync(0xffffffffu, ls0, 1);
        ls0 += __shfl_xor_sync(0xffffffffu, ls0, 2);
        ls1 += __shfl_xor_sync(0xffffffffu, ls1, 1);
        ls1 += __shfl_xor_sync(0xffffffffu, ls1, 2);
        l0 = l0 * al0 + ls0;
        l1 = l1 * al1 + ls1;
        m0 = mn0; m1 = mn1;
#pragma unroll
        for (int t = 0; t < 8; t++) {
            O[t][0] *= al0; O[t][1] *= al0;
            O[t][2] *= al1; O[t][3] *= al1;
        }

#pragma unroll
        for (int t = 0; t < 8; t++) {
#pragma unroll
            for (int kc = 0; kc < 4; kc++) {
                int vr = (kc * 16 + qc) * 72 + t * 8 + gid;
                __half x0 = VTs[vr];
                __half x1 = VTs[vr + 72];
                __half x2 = VTs[vr + 8 * 72];
                __half x3 = VTs[vr + 9 * 72];
                mma16816(O[t], pA[kc], h2u(x0, x1), h2u(x2, x3));
            }
        }
    }

    float inv0 = 1.f / l0, inv1 = 1.f / l1;
#pragma unroll
    for (int t = 0; t < 8; t++) {
        *(__half2*)(ctx + (size_t)(qrow0 + gid) * DMODEL + hc + t * 8 + qc) =
            __floats2half2_rn(O[t][0] * inv0, O[t][1] * inv0);
        *(__half2*)(ctx + (size_t)(qrow0 + gid + 8) * DMODEL + hc + t * 8 + qc) =
            __floats2half2_rn(O[t][2] * inv1, O[t][3] * inv1);
    }
}

// ---------------------------------------------------------------------------
// LayerNorm over 1024 cols, block=256, one row per block. Optional fp16 copy.
// ---------------------------------------------------------------------------
__global__ void __launch_bounds__(256) ln_kernel(
    const float* __restrict__ in, const float* __restrict__ g,
    const float* __restrict__ be, float* __restrict__ outf,
    __half* __restrict__ outh)
{
    int row = blockIdx.x;
    int tid = threadIdx.x;
    float4 v = ((const float4*)(in + (size_t)row * DMODEL))[tid];
    float s  = v.x + v.y + v.z + v.w;
    float ss = v.x * v.x + v.y * v.y + v.z * v.z + v.w * v.w;
#pragma unroll
    for (int o = 16; o > 0; o >>= 1) {
        s  += __shfl_down_sync(0xffffffffu, s, o);
        ss += __shfl_down_sync(0xffffffffu, ss, o);
    }
    __shared__ float shs[8], shss[8], smu, srs;
    int lane = tid & 31, wid = tid >> 5;
    if (lane == 0) { shs[wid] = s; shss[wid] = ss; }
    __syncthreads();
    if (tid == 0) {
        float S = 0.f, SS = 0.f;
#pragma unroll
        for (int i = 0; i < 8; i++) { S += shs[i]; SS += shss[i]; }
        float mu = S * (1.f / 1024.f);
        float var = SS * (1.f / 1024.f) - mu * mu;
        smu = mu;
        srs = rsqrtf(var + 1e-5f);
    }
    __syncthreads();
    float mu = smu, rs = srs;
    float4 gv = ((const float4*)g)[tid];
    float4 bv = ((const float4*)be)[tid];
    float4 o;
    o.x = (v.x - mu) * rs * gv.x + bv.x;
    o.y = (v.y - mu) * rs * gv.y + bv.y;
    o.z = (v.z - mu) * rs * gv.z + bv.z;
    o.w = (v.w - mu) * rs * gv.w + bv.w;
    ((float4*)(outf + (size_t)row * DMODEL))[tid] = o;
    if (outh) {
        ((__half2*)(outh + (size_t)row * DMODEL))[2 * tid]     = __floats2half2_rn(o.x, o.y);
        ((__half2*)(outh + (size_t)row * DMODEL))[2 * tid + 1] = __floats2half2_rn(o.z, o.w);
    }
}

extern "C" void kernel_launch(void* const* d_in, const int* in_sizes, int n_in,
                              void* d_out, int out_size) {
    const float* x   = (const float*)d_in[0];
    const float* wq  = (const float*)d_in[1];
    const float* bq  = (const float*)d_in[2];
    const float* wk  = (const float*)d_in[3];
    const float* bk  = (const float*)d_in[4];
    const float* wv  = (const float*)d_in[5];
    const float* bv  = (const float*)d_in[6];
    const float* wo  = (const float*)d_in[7];
    const float* bo  = (const float*)d_in[8];
    const float* w1  = (const float*)d_in[9];
    const float* b1  = (const float*)d_in[10];
    const float* w2  = (const float*)d_in[11];
    const float* b2  = (const float*)d_in[12];
    const float* g1  = (const float*)d_in[13];
    const float* be1 = (const float*)d_in[14];
    const float* g2  = (const float*)d_in[15];
    const float* be2 = (const float*)d_in[16];
    float* out = (float*)d_out;

    void *p;
    cudaGetSymbolAddress(&p, g_xh);   __half* xh  = (__half*)p;
    cudaGetSymbolAddress(&p, g_xl);   __half* xl  = (__half*)p;
    cudaGetSymbolAddress(&p, g_wqh);  __half* wqh = (__half*)p;
    cudaGetSymbolAddress(&p, g_wql);  __half* wql = (__half*)p;
    cudaGetSymbolAddress(&p, g_wkh);  __half* wkh = (__half*)p;
    cudaGetSymbolAddress(&p, g_wkl);  __half* wkl = (__half*)p;
    cudaGetSymbolAddress(&p, g_wvh);  __half* wvh = (__half*)p;
    cudaGetSymbolAddress(&p, g_woh);  __half* woh = (__half*)p;
    cudaGetSymbolAddress(&p, g_w1h);  __half* w1h = (__half*)p;
    cudaGetSymbolAddress(&p, g_w2h);  __half* w2h = (__half*)p;
    cudaGetSymbolAddress(&p, g_qrh);  __half* qrh = (__half*)p;
    cudaGetSymbolAddress(&p, g_qrl);  __half* qrl = (__half*)p;
    cudaGetSymbolAddress(&p, g_krh);  __half* krh = (__half*)p;
    cudaGetSymbolAddress(&p, g_krl);  __half* krl = (__half*)p;
    cudaGetSymbolAddress(&p, g_vh);   __half* vh  = (__half*)p;
    cudaGetSymbolAddress(&p, g_ctx);  __half* ctx = (__half*)p;
    cudaGetSymbolAddress(&p, g_res1); float*  res1 = (float*)p;
    cudaGetSymbolAddress(&p, g_hbuf); float*  hbuf = (float*)p;
    cudaGetSymbolAddress(&p, g_hh);   __half* hh  = (__half*)p;
    cudaGetSymbolAddress(&p, g_ff1);  __half* ff1 = (__half*)p;
    cudaGetSymbolAddress(&p, g_res2); float*  res2 = (float*)p;

    cudaFuncSetAttribute(gemm_h<false, false, false, true>,
                         cudaFuncAttributeMaxDynamicSharedMemorySize, GH_SMEM);
    cudaFuncSetAttribute(gemm_h<false, true, true, false>,
                         cudaFuncAttributeMaxDynamicSharedMemorySize, GH_SMEM);
    cudaFuncSetAttribute(gemm_h<true, false, false, true>,
                         cudaFuncAttributeMaxDynamicSharedMemorySize, GH_SMEM);
    cudaFuncSetAttribute(gemm_split_rope,
                         cudaFuncAttributeMaxDynamicSharedMemorySize, GS_SMEM);
    cudaFuncSetAttribute(attn_kernel,
                         cudaFuncAttributeMaxDynamicSharedMemorySize, ATT_SMEM);

    // launch 0: all conversions fused
    conv_all<<<CV_B6 / 256, 256>>>(x, wq, wk, wv, wo, w1, w2,
                                   xh, xl, wqh, wql, wkh, wkl, wvh, woh, w1h, w2h);

    dim3 grid1(DMODEL / 128, ROWS / 128);   // (8, 64)
    dim3 gridF(DFF / 128,    ROWS / 128);   // (32, 64)

    // launch 1: V projection (plain fp16)
    gemm_h<false, false, false, true><<<grid1, 256, GH_SMEM>>>(xh, wvh, bv, nullptr, nullptr, vh, ROWS, DMODEL, DMODEL);

    // launches 2-3: Q,K split projections with fused rope (hi/lo fp16 out)
    gemm_split_rope<<<grid1, 256, GS_SMEM>>>(xh, xl, wqh, wql, bq, qrh, qrl, 0.125f, ROWS, DMODEL, DMODEL);
    gemm_split_rope<<<grid1, 256, GS_SMEM>>>(xh, xl, wkh, wkl, bk, krh, krl, 1.0f,   ROWS, DMODEL, DMODEL);

    // launch 4: attention (register-resident FA2)
    attn_kernel<<<dim3(SEQ / 64, NHEADS, BATCH), 128, ATT_SMEM>>>(qrh, qrl, krh, krl, vh, ctx);

    // launch 5: output projection + residual(x)
    gemm_h<false, true, true, false><<<grid1, 256, GH_SMEM>>>(ctx, woh, bo, x, res1, nullptr, ROWS, DMODEL, DMODEL);

    // LN1 -> h (fp32 + fp16)
    ln_kernel<<<ROWS, 256>>>(res1, g1, be1, hbuf, hh);

    // FFN
    gemm_h<true,  false, false, true ><<<gridF, 256, GH_SMEM>>>(hh, w1h, b1, nullptr, nullptr, ff1, ROWS, DFF, DMODEL);
    gemm_h<false, true,  true,  false><<<grid1, 256, GH_SMEM>>>(ff1, w2h, b2, hbuf, res2, nullptr, ROWS, DMODEL, DFF);

    // LN2 -> output
    ln_kernel<<<ROWS, 256>>>(res2, g2, be2, out, nullptr);
}